// round 10
// baseline (speedup 1.0000x reference)
#include <cuda_runtime.h>
#include <cuda_bf16.h>
#include <math.h>
#include <stdint.h>

#define NS 2048
#define NB 2
#define NH 16
#define NDK 64
#define ND 1024
#define MT (NB*NS)          // 4096 rows total
#define QKV_N (3*ND)        // 3072

// single dynamic-shared symbol for the whole TU (kernels cast as needed)
extern __shared__ char dynsm[];

// Scratch (allocation-free rule: __device__ globals)
__device__ __nv_bfloat16 g_Xhi[MT*ND];
__device__ __nv_bfloat16 g_Xlo[MT*ND];
__device__ __nv_bfloat16 g_Whi[QKV_N*ND];
__device__ __nv_bfloat16 g_Wlo[QKV_N*ND];
__device__ __nv_bfloat16 g_Ohi[ND*ND];
__device__ __nv_bfloat16 g_Olo[ND*ND];
__device__ __nv_bfloat16 g_AOhi[MT*ND];
__device__ __nv_bfloat16 g_AOlo[MT*ND];
__device__ __nv_bfloat16 g_Qhi[NB*NH*NS*NDK];   // [b][h][s][d]
__device__ __nv_bfloat16 g_Qlo[NB*NH*NS*NDK];
__device__ __nv_bfloat16 g_Khi[NB*NH*NS*NDK];
__device__ __nv_bfloat16 g_Klo[NB*NH*NS*NDK];
__device__ __nv_bfloat16 g_Vhi[NB*NH*NS*NDK];
__device__ __nv_bfloat16 g_Vlo[NB*NH*NS*NDK];

// ---------------------------------------------------------------------------
// helpers (portable PTX only: mma.sync / ldmatrix / cp.async — no tcgen05)
// ---------------------------------------------------------------------------
__device__ __forceinline__ uint32_t smem_u32(const void* p){
    uint32_t a;
    asm("{ .reg .u64 t; cvta.to.shared.u64 t, %1; cvt.u32.u64 %0, t; }" : "=r"(a) : "l"(p));
    return a;
}
__device__ __forceinline__ void cp16(uint32_t saddr, const void* g){
    asm volatile("cp.async.cg.shared.global [%0], [%1], 16;" :: "r"(saddr), "l"(g));
}
__device__ __forceinline__ void cp_commit(){
    asm volatile("cp.async.commit_group;" ::: "memory");
}
__device__ __forceinline__ void ldsm_x4(uint32_t r[4], uint32_t addr){
    asm volatile("ldmatrix.sync.aligned.m8n8.x4.shared.b16 {%0,%1,%2,%3}, [%4];"
                 : "=r"(r[0]), "=r"(r[1]), "=r"(r[2]), "=r"(r[3]) : "r"(addr));
}
__device__ __forceinline__ void ldsm_x4_t(uint32_t r[4], uint32_t addr){
    asm volatile("ldmatrix.sync.aligned.m8n8.x4.trans.shared.b16 {%0,%1,%2,%3}, [%4];"
                 : "=r"(r[0]), "=r"(r[1]), "=r"(r[2]), "=r"(r[3]) : "r"(addr));
}
__device__ __forceinline__ void mma_bf16(float c[4], const uint32_t a[4],
                                         const uint32_t b0, const uint32_t b1){
    asm volatile(
        "mma.sync.aligned.m16n8k16.row.col.f32.bf16.bf16.f32 "
        "{%0,%1,%2,%3}, {%4,%5,%6,%7}, {%8,%9}, {%0,%1,%2,%3};"
        : "+f"(c[0]), "+f"(c[1]), "+f"(c[2]), "+f"(c[3])
        : "r"(a[0]), "r"(a[1]), "r"(a[2]), "r"(a[3]), "r"(b0), "r"(b1));
}
__device__ __forceinline__ uint32_t packbf(float a, float b){
    __nv_bfloat162 t = __floats2bfloat162_rn(a, b);
    return *(uint32_t*)&t;
}

// ---------------------------------------------------------------------------
// fp32 -> (bf16 hi, bf16 lo) split. which: 0=X, 1=Wqkv, 2=Wout
// ---------------------------------------------------------------------------
__global__ void __launch_bounds__(256)
split_convert(const float* __restrict__ src, int which, int n4)
{
    int i = blockIdx.x * 256 + threadIdx.x;
    if (i >= n4) return;
    __nv_bfloat16 *hi, *lo;
    if (which == 0)      { hi = g_Xhi; lo = g_Xlo; }
    else if (which == 1) { hi = g_Whi; lo = g_Wlo; }
    else                 { hi = g_Ohi; lo = g_Olo; }
    float4 v = ((const float4*)src)[i];
    __nv_bfloat16 h0 = __float2bfloat16(v.x);
    __nv_bfloat16 h1 = __float2bfloat16(v.y);
    __nv_bfloat16 h2 = __float2bfloat16(v.z);
    __nv_bfloat16 h3 = __float2bfloat16(v.w);
    __nv_bfloat16 l0 = __float2bfloat16(v.x - __bfloat162float(h0));
    __nv_bfloat16 l1 = __float2bfloat16(v.y - __bfloat162float(h1));
    __nv_bfloat16 l2 = __float2bfloat16(v.z - __bfloat162float(h2));
    __nv_bfloat16 l3 = __float2bfloat16(v.w - __bfloat162float(h3));
    ((__nv_bfloat162*)hi)[2*i]   = __halves2bfloat162(h0, h1);
    ((__nv_bfloat162*)hi)[2*i+1] = __halves2bfloat162(h2, h3);
    ((__nv_bfloat162*)lo)[2*i]   = __halves2bfloat162(l0, l1);
    ((__nv_bfloat162*)lo)[2*i+1] = __halves2bfloat162(l2, l3);
}

// ---------------------------------------------------------------------------
// Split-bf16 warp-MMA GEMM: C[m,n] = sum_k A[m,k]*B[n,k], K=1024.
// CTA tile 256x128, 16 warps (4m x 4n), warp tile 64x32, K chunk 64,
// 2-stage cp.async pipeline, XOR-swizzled rows, 3 passes (hh, hl, lh).
// 512 threads -> 4 warps/SMSP for latency hiding.
// mode 1: A=Xhi/lo, B=Wqkv hi/lo -> scatter bf16 hi/lo into g_{Q,K,V}{hi,lo}.
// mode 0: A=AO hi/lo, B=Wout hi/lo -> Cout [MT x ND] fp32.
// ---------------------------------------------------------------------------
#define KC 64
#define GTHREADS 512
#define A_ARR (256*128)                 // 256 rows x 128B = 32KB
#define B_ARR (128*128)                 // 128 rows x 128B = 16KB
#define STAGE_BYTES (2*A_ARR + 2*B_ARR) // 96KB
#define GEMM_SMEM (2*STAGE_BYTES)       // 192KB (epilogue reuses it)

__global__ void __launch_bounds__(GTHREADS, 1)
gemm_split_kernel(float* __restrict__ Cout, int mode)
{
    char* sm = dynsm;
    const int tid = threadIdx.x;
    const int wid = tid >> 5, lane = tid & 31;
    const int m0 = blockIdx.y * 256;
    const int n0 = blockIdx.x * 128;

    const __nv_bfloat16 *Ahi, *Alo, *Bhi, *Blo;
    if (mode == 1) { Ahi = g_Xhi;  Alo = g_Xlo;  Bhi = g_Whi; Blo = g_Wlo; }
    else           { Ahi = g_AOhi; Alo = g_AOlo; Bhi = g_Ohi; Blo = g_Olo; }

    const uint32_t smb = smem_u32(sm);

    // warp layout: 4 (m) x 4 (n); warp tile 64x32
    const int wm0 = (wid >> 2) * 64;
    const int wn0 = (wid & 3) * 32;

    float acc[4][4][4];
#pragma unroll
    for (int a = 0; a < 4; a++)
#pragma unroll
        for (int b = 0; b < 4; b++)
#pragma unroll
            for (int c = 0; c < 4; c++) acc[a][b][c] = 0.f;

    // ---- global -> smem stage loader (cp.async, 12 x 16B per thread) ----
    auto load_stage = [&](int stage, int k0) {
        uint32_t sb = smb + stage * STAGE_BYTES;
        // A hi/lo: 256 rows each (2048 16B-chunks per array)
#pragma unroll
        for (int c = 0; c < 4; c++) {
            int linear = c * GTHREADS + tid;   // 0..2047
            int row = linear >> 3;             // 0..255
            int cb  = linear & 7;
            uint32_t off = row * 128 + ((cb ^ (row & 7)) << 4);
            const size_t g = (size_t)(m0 + row) * ND + k0 + cb * 8;
            cp16(sb + off,         Ahi + g);
            cp16(sb + A_ARR + off, Alo + g);
        }
        // B hi/lo: 128 rows each (1024 chunks per array)
#pragma unroll
        for (int c = 0; c < 2; c++) {
            int linear = c * GTHREADS + tid;   // 0..1023
            int row = linear >> 3;             // 0..127
            int cb  = linear & 7;
            uint32_t off = row * 128 + ((cb ^ (row & 7)) << 4);
            const size_t g = (size_t)(n0 + row) * ND + k0 + cb * 8;
            cp16(sb + 2*A_ARR + off,         Bhi + g);
            cp16(sb + 2*A_ARR + B_ARR + off, Blo + g);
        }
        cp_commit();
    };

    load_stage(0, 0);

#pragma unroll 1
    for (int i = 0; i < 16; i++) {
        if (i < 15) load_stage((i + 1) & 1, (i + 1) * KC);
        if (i < 15) asm volatile("cp.async.wait_group 1;" ::: "memory");
        else        asm volatile("cp.async.wait_group 0;" ::: "memory");
        __syncthreads();

        uint32_t sb = smb + (i & 1) * STAGE_BYTES;
        uint32_t a_hi_b = sb, a_lo_b = sb + A_ARR;
        uint32_t b_hi_b = sb + 2*A_ARR, b_lo_b = sb + 2*A_ARR + B_ARR;

#pragma unroll
        for (int ks = 0; ks < 4; ks++) {
            // A fragments: 4 m16 tiles, hi+lo
            uint32_t ah[4][4], al[4][4];
            {
                int row = (lane & 15);
                int kb  = ks * 2 + (lane >> 4);
#pragma unroll
                for (int mt = 0; mt < 4; mt++) {
                    int r = wm0 + mt * 16 + row;
                    uint32_t off = r * 128 + (((uint32_t)(kb ^ (r & 7))) << 4);
                    ldsm_x4(ah[mt], a_hi_b + off);
                    ldsm_x4(al[mt], a_lo_b + off);
                }
            }
            // B: 2 chunks of 2 n8-tiles; load + consume per chunk
            int g = lane >> 3, trow = lane & 7;
#pragma unroll
            for (int p = 0; p < 2; p++) {
                int nrow = wn0 + (p * 2 + (g >> 1)) * 8 + trow;
                int kb = ks * 2 + (g & 1);
                uint32_t off = nrow * 128 + (((uint32_t)(kb ^ (nrow & 7))) << 4);
                uint32_t bh[4], bl[4];
                ldsm_x4(bh, b_hi_b + off);
                ldsm_x4(bl, b_lo_b + off);
#pragma unroll
                for (int mt = 0; mt < 4; mt++) {
                    float* a0 = acc[mt][p*2];
                    float* a1 = acc[mt][p*2+1];
                    mma_bf16(a0, ah[mt], bh[0], bh[1]);
                    mma_bf16(a0, ah[mt], bl[0], bl[1]);
                    mma_bf16(a0, al[mt], bh[0], bh[1]);
                    mma_bf16(a1, ah[mt], bh[2], bh[3]);
                    mma_bf16(a1, ah[mt], bl[2], bl[3]);
                    mma_bf16(a1, al[mt], bh[2], bh[3]);
                }
            }
        }
        __syncthreads();
    }

    // ---- epilogue: acc -> smem (256x132 f32) -> vectorized global ----
    float* sf = (float*)sm;
    const int gq = lane >> 2, tq = lane & 3;
#pragma unroll
    for (int mt = 0; mt < 4; mt++)
#pragma unroll
        for (int nt = 0; nt < 4; nt++) {
            int m = wm0 + mt * 16 + gq;
            int n = wn0 + nt * 8 + 2 * tq;
            sf[m * 132 + n]           = acc[mt][nt][0];
            sf[m * 132 + n + 1]       = acc[mt][nt][1];
            sf[(m + 8) * 132 + n]     = acc[mt][nt][2];
            sf[(m + 8) * 132 + n + 1] = acc[mt][nt][3];
        }
    __syncthreads();

    // each thread: 16 consecutive cols of one row per pass, 4 passes
    const int rr   = tid >> 3;          // 0..63
    const int colg = (tid & 7) * 16;    // 0,16,...,112
#pragma unroll 1
    for (int pass = 0; pass < 4; pass++) {
        int r = pass * 64 + rr;
        const float* src = &sf[r * 132 + colg];
        if (mode == 0) {
            float4* dst = (float4*)&Cout[(size_t)(m0 + r) * ND + n0 + colg];
#pragma unroll
            for (int j = 0; j < 4; j++) dst[j] = ((const float4*)src)[j];
        } else {
            int col0 = n0 + colg;
            int part = col0 >> 10;
            int rem  = col0 & 1023;
            int h    = rem >> 6;
            int d0   = rem & 63;
            __nv_bfloat16 *dhi, *dlo;
            if (part == 0)      { dhi = g_Qhi; dlo = g_Qlo; }
            else if (part == 1) { dhi = g_Khi; dlo = g_Klo; }
            else                { dhi = g_Vhi; dlo = g_Vlo; }
            int m = m0 + r;
            int b = m >> 11, s = m & 2047;
            size_t base = (((size_t)(b * NH + h)) * NS + s) * NDK + d0;
            uint32_t hp[8], lp[8];
#pragma unroll
            for (int j = 0; j < 8; j++) {
                float v0 = src[2*j], v1 = src[2*j+1];
                float h0 = __bfloat162float(__float2bfloat16(v0));
                float h1 = __bfloat162float(__float2bfloat16(v1));
                hp[j] = packbf(v0, v1);
                lp[j] = packbf(v0 - h0, v1 - h1);
            }
            ((uint4*)&dhi[base])[0] = make_uint4(hp[0], hp[1], hp[2], hp[3]);
            ((uint4*)&dhi[base])[1] = make_uint4(hp[4], hp[5], hp[6], hp[7]);
            ((uint4*)&dlo[base])[0] = make_uint4(lp[0], lp[1], lp[2], lp[3]);
            ((uint4*)&dlo[base])[1] = make_uint4(lp[4], lp[5], lp[6], lp[7]);
        }
    }
}

// ---------------------------------------------------------------------------
// Stage 2: causal flash attention on mma.sync, split-bf16 throughout.
// BQ=128 (8 warps x 16 rows), BK=64, double-buffered K/V via cp.async.
// grid = (16 qtiles [reversed], 32 bh)
// ---------------------------------------------------------------------------
#define BQ 128
#define ATTN_SMEM_B (32768 + 2*32768)   // Q hi/lo 32KB + 2 stages x (K/V hi/lo 32KB)

__global__ void __launch_bounds__(256, 1)
attn_mma_kernel()
{
    const uint32_t smb = smem_u32(dynsm);
    const int tid = threadIdx.x;
    const int wid = tid >> 5, lane = tid & 31;
    const int qb = 15 - (int)blockIdx.x;      // biggest q-tiles first
    const int bh = blockIdx.y;
    const int q0 = qb * BQ;
    const int nkt = 2*qb + 2;

    const size_t bho = (size_t)bh * NS * NDK;
    const __nv_bfloat16* Qhg = g_Qhi + bho;
    const __nv_bfloat16* Qlg = g_Qlo + bho;
    const __nv_bfloat16* Khg = g_Khi + bho;
    const __nv_bfloat16* Klg = g_Klo + bho;
    const __nv_bfloat16* Vhg = g_Vhi + bho;
    const __nv_bfloat16* Vlg = g_Vlo + bho;

    // prologue: Q tile (128 x 64 hi/lo) -> smem [row][d] swizzled
#pragma unroll
    for (int c = 0; c < 4; c++) {
        int linear = c*256 + tid;
        int row = linear >> 3, cb = linear & 7;
        uint32_t sa = smb + row*128 + ((cb ^ (row & 7)) << 4);
        cp16(sa,         Qhg + (size_t)(q0 + row)*NDK + cb*8);
        cp16(sa + 16384, Qlg + (size_t)(q0 + row)*NDK + cb*8);
    }
    auto load_stage = [&](int stage, int k0){
        uint32_t sb = smb + 32768 + stage*32768;
        const __nv_bfloat16* srcs[4] = {Khg, Klg, Vhg, Vlg};
#pragma unroll
        for (int arr = 0; arr < 4; arr++) {
#pragma unroll
            for (int c = 0; c < 2; c++) {
                int linear = c*256 + tid;
                int row = linear >> 3, cb = linear & 7;
                uint32_t sa = sb + arr*8192 + row*128 + ((cb ^ (row & 7)) << 4);
                cp16(sa, srcs[arr] + (size_t)(k0 + row)*NDK + cb*8);
            }
        }
        cp_commit();
    };
    load_stage(0, 0);
    asm volatile("cp.async.wait_group 0;" ::: "memory");
    __syncthreads();

    uint32_t qh[4][4], ql[4][4];
    {
        int r = wid*16 + (lane & 15);
#pragma unroll
        for (int ks = 0; ks < 4; ks++) {
            int cb = ks*2 + (lane >> 4);
            uint32_t off = r*128 + (((uint32_t)(cb ^ (r & 7))) << 4);
            ldsm_x4(qh[ks], smb + off);
            ldsm_x4(ql[ks], smb + 16384 + off);
        }
    }

    float o[8][4];
#pragma unroll
    for (int nt = 0; nt < 8; nt++)
#pragma unroll
        for (int f = 0; f < 4; f++) o[nt][f] = 0.f;
    float mrow[2] = {-INFINITY, -INFINITY};
    float lrow[2] = {0.f, 0.f};

#pragma unroll 1
    for (int kt = 0; kt < nkt; kt++) {
        if (kt + 1 < nkt) {
            load_stage((kt + 1) & 1, (kt + 1) * 64);
            asm volatile("cp.async.wait_group 1;" ::: "memory");
        } else {
            asm volatile("cp.async.wait_group 0;" ::: "memory");
        }
        __syncthreads();
        uint32_t sb = smb + 32768 + (kt & 1)*32768;

        // ---- S = Q.K^T (split 3-pass), 16x64 per warp ----
        float s[8][4];
#pragma unroll
        for (int nt = 0; nt < 8; nt++)
#pragma unroll
            for (int f = 0; f < 4; f++) s[nt][f] = 0.f;

#pragma unroll
        for (int ks = 0; ks < 4; ks++) {
#pragma unroll
            for (int half = 0; half < 2; half++) {
                uint32_t kh4[4][2], kl4[4][2];
                int g = lane >> 3, trow = lane & 7;
#pragma unroll
                for (int p = 0; p < 2; p++) {
                    int nrow = half*32 + (p*2 + (g >> 1))*8 + trow;
                    int kb = ks*2 + (g & 1);
                    uint32_t off = nrow*128 + (((uint32_t)(kb ^ (nrow & 7))) << 4);
                    uint32_t r4[4];
                    ldsm_x4(r4, sb + off);
                    kh4[p*2][0] = r4[0]; kh4[p*2][1] = r4[1];
                    kh4[p*2+1][0] = r4[2]; kh4[p*2+1][1] = r4[3];
                    ldsm_x4(r4, sb + 8192 + off);
                    kl4[p*2][0] = r4[0]; kl4[p*2][1] = r4[1];
                    kl4[p*2+1][0] = r4[2]; kl4[p*2+1][1] = r4[3];
                }
#pragma unroll
                for (int nt = 0; nt < 4; nt++) {
                    float* acc = s[half*4 + nt];
                    mma_bf16(acc, qh[ks], kh4[nt][0], kh4[nt][1]);
                    mma_bf16(acc, qh[ks], kl4[nt][0], kl4[nt][1]);
                    mma_bf16(acc, ql[ks], kh4[nt][0], kh4[nt][1]);
                }
            }
        }

        // ---- scale + causal mask ----
#pragma unroll
        for (int nt = 0; nt < 8; nt++)
#pragma unroll
            for (int f = 0; f < 4; f++) s[nt][f] *= 0.125f;
        if (kt >= nkt - 2) {
            int lim0 = q0 + wid*16 + (lane >> 2) - kt*64;
#pragma unroll
            for (int nt = 0; nt < 8; nt++) {
                int cb = nt*8 + (lane & 3)*2;
                if (cb     > lim0)     s[nt][0] = -INFINITY;
                if (cb + 1 > lim0)     s[nt][1] = -INFINITY;
                if (cb     > lim0 + 8) s[nt][2] = -INFINITY;
                if (cb + 1 > lim0 + 8) s[nt][3] = -INFINITY;
            }
        }

        // ---- online softmax in fragments; pack P hi/lo ----
        uint32_t phi[8][2], plo[8][2];
#pragma unroll
        for (int rh = 0; rh < 2; rh++) {
            float tm = -INFINITY;
#pragma unroll
            for (int nt = 0; nt < 8; nt++)
                tm = fmaxf(tm, fmaxf(s[nt][2*rh], s[nt][2*rh+1]));
            tm = fmaxf(tm, __shfl_xor_sync(0xffffffffu, tm, 1));
            tm = fmaxf(tm, __shfl_xor_sync(0xffffffffu, tm, 2));
            float mn  = fmaxf(mrow[rh], tm);
            float sc  = __expf(mrow[rh] - mn);
            float sum = 0.f;
#pragma unroll
            for (int nt = 0; nt < 8; nt++) {
                float p0 = __expf(s[nt][2*rh]     - mn);
                float p1 = __expf(s[nt][2*rh + 1] - mn);
                sum += p0 + p1;
                float h0 = __bfloat162float(__float2bfloat16(p0));
                float h1 = __bfloat162float(__float2bfloat16(p1));
                phi[nt][rh] = packbf(p0, p1);
                plo[nt][rh] = packbf(p0 - h0, p1 - h1);
            }
            sum += __shfl_xor_sync(0xffffffffu, sum, 1);
            sum += __shfl_xor_sync(0xffffffffu, sum, 2);
            lrow[rh] = lrow[rh]*sc + sum;
            mrow[rh] = mn;
#pragma unroll
            for (int nt = 0; nt < 8; nt++) {
                o[nt][2*rh]     *= sc;
                o[nt][2*rh + 1] *= sc;
            }
        }

        // ---- O += P.V (split 3-pass), V via ldmatrix.trans on [key][d] ----
#pragma unroll
        for (int ks = 0; ks < 4; ks++) {
            uint32_t aph[4] = {phi[2*ks][0], phi[2*ks][1], phi[2*ks+1][0], phi[2*ks+1][1]};
            uint32_t apl[4] = {plo[2*ks][0], plo[2*ks][1], plo[2*ks+1][0], plo[2*ks+1][1]};
#pragma unroll
            for (int dh = 0; dh < 4; dh++) {
                int r  = 16*ks + (lane & 15);
                int cb = dh*2 + (lane >> 4);
                uint32_t off = r*128 + (((uint32_t)(cb ^ (r & 7))) << 4);
                uint32_t vh[4], vl[4];
                ldsm_x4_t(vh, sb + 16384 + off);
                ldsm_x4_t(vl, sb + 24576 + off);
                mma_bf16(o[dh*2],   aph, vh[0], vh[1]);
                mma_bf16(o[dh*2],   aph, vl[0], vl[1]);
                mma_bf16(o[dh*2],   apl, vh[0], vh[1]);
                mma_bf16(o[dh*2+1], aph, vh[2], vh[3]);
                mma_bf16(o[dh*2+1], aph, vl[2], vl[3]);
                mma_bf16(o[dh*2+1], apl, vh[2], vh[3]);
            }
        }
        __syncthreads();
    }

    // ---- epilogue: O / l -> split bf16 hi/lo at [b*s][h*dk] ----
    const int b = bh >> 4, h = bh & 15;
#pragma unroll
    for (int rh = 0; rh < 2; rh++) {
        float inv = 1.0f / lrow[rh];
        int qrow = q0 + wid*16 + (lane >> 2) + rh*8;
        size_t rowbase = ((size_t)(b*NS + qrow))*ND + h*NDK;
#pragma unroll
        for (int nt = 0; nt < 8; nt++) {
            float v0 = o[nt][2*rh]     * inv;
            float v1 = o[nt][2*rh + 1] * inv;
            size_t idx = rowbase + nt*8 + (lane & 3)*2;
            float h0 = __bfloat162float(__float2bfloat16(v0));
            float h1 = __bfloat162float(__float2bfloat16(v1));
            *(uint32_t*)&g_AOhi[idx] = packbf(v0, v1);
            *(uint32_t*)&g_AOlo[idx] = packbf(v0 - h0, v1 - h1);
        }
    }
}

// ---------------------------------------------------------------------------

extern "C" void kernel_launch(void* const* d_in, const int* in_sizes, int n_in,
                              void* d_out, int out_size)
{
    const float* X    = (const float*)d_in[0];   // [2,2048,1024]
    const float* Wqkv = (const float*)d_in[1];   // [3072,1024]
    const float* Wout = (const float*)d_in[2];   // [1024,1024]
    float* out = (float*)d_out;                  // [2,2048,1024]

    cudaFuncSetAttribute(gemm_split_kernel, cudaFuncAttributeMaxDynamicSharedMemorySize, GEMM_SMEM);
    cudaFuncSetAttribute(attn_mma_kernel,  cudaFuncAttributeMaxDynamicSharedMemorySize, ATTN_SMEM_B);

    split_convert<<<(MT*ND/4)/256,    256>>>(X,    0, MT*ND/4);
    split_convert<<<(QKV_N*ND/4)/256, 256>>>(Wqkv, 1, QKV_N*ND/4);
    split_convert<<<(ND*ND/4)/256,    256>>>(Wout, 2, ND*ND/4);

    gemm_split_kernel<<<dim3(QKV_N/128, MT/256), GTHREADS, GEMM_SMEM>>>(nullptr, 1);
    attn_mma_kernel<<<dim3(NS/BQ, NB*NH), 256, ATTN_SMEM_B>>>();
    gemm_split_kernel<<<dim3(ND/128, MT/256), GTHREADS, GEMM_SMEM>>>(out, 0);
}

// round 11
// speedup vs baseline: 1.0173x; 1.0173x over previous
#include <cuda_runtime.h>
#include <cuda_bf16.h>
#include <math.h>
#include <stdint.h>

#define NS 2048
#define NB 2
#define NH 16
#define NDK 64
#define ND 1024
#define MT (NB*NS)          // 4096 rows total
#define QKV_N (3*ND)        // 3072

// single dynamic-shared symbol for the whole TU (kernels cast as needed)
extern __shared__ char dynsm[];

// Scratch (allocation-free rule: __device__ globals)
__device__ __nv_bfloat16 g_Xhi[MT*ND];
__device__ __nv_bfloat16 g_Xlo[MT*ND];
__device__ __nv_bfloat16 g_Whi[QKV_N*ND];
__device__ __nv_bfloat16 g_Wlo[QKV_N*ND];
__device__ __nv_bfloat16 g_Ohi[ND*ND];
__device__ __nv_bfloat16 g_Olo[ND*ND];
__device__ __nv_bfloat16 g_AOhi[MT*ND];
__device__ __nv_bfloat16 g_AOlo[MT*ND];
__device__ __nv_bfloat16 g_Qhi[NB*NH*NS*NDK];   // [b][h][s][d]
__device__ __nv_bfloat16 g_Qlo[NB*NH*NS*NDK];
__device__ __nv_bfloat16 g_Khi[NB*NH*NS*NDK];
__device__ __nv_bfloat16 g_Klo[NB*NH*NS*NDK];
__device__ __nv_bfloat16 g_Vhi[NB*NH*NS*NDK];
__device__ __nv_bfloat16 g_Vlo[NB*NH*NS*NDK];

// ---------------------------------------------------------------------------
// helpers (portable PTX only: mma.sync / ldmatrix / cp.async — no tcgen05)
// ---------------------------------------------------------------------------
__device__ __forceinline__ uint32_t smem_u32(const void* p){
    uint32_t a;
    asm("{ .reg .u64 t; cvta.to.shared.u64 t, %1; cvt.u32.u64 %0, t; }" : "=r"(a) : "l"(p));
    return a;
}
__device__ __forceinline__ void cp16(uint32_t saddr, const void* g){
    asm volatile("cp.async.cg.shared.global [%0], [%1], 16;" :: "r"(saddr), "l"(g));
}
__device__ __forceinline__ void cp_commit(){
    asm volatile("cp.async.commit_group;" ::: "memory");
}
__device__ __forceinline__ void ldsm_x4(uint32_t r[4], uint32_t addr){
    asm volatile("ldmatrix.sync.aligned.m8n8.x4.shared.b16 {%0,%1,%2,%3}, [%4];"
                 : "=r"(r[0]), "=r"(r[1]), "=r"(r[2]), "=r"(r[3]) : "r"(addr));
}
__device__ __forceinline__ void ldsm_x4_t(uint32_t r[4], uint32_t addr){
    asm volatile("ldmatrix.sync.aligned.m8n8.x4.trans.shared.b16 {%0,%1,%2,%3}, [%4];"
                 : "=r"(r[0]), "=r"(r[1]), "=r"(r[2]), "=r"(r[3]) : "r"(addr));
}
__device__ __forceinline__ void mma_bf16(float c[4], const uint32_t a[4],
                                         const uint32_t b0, const uint32_t b1){
    asm volatile(
        "mma.sync.aligned.m16n8k16.row.col.f32.bf16.bf16.f32 "
        "{%0,%1,%2,%3}, {%4,%5,%6,%7}, {%8,%9}, {%0,%1,%2,%3};"
        : "+f"(c[0]), "+f"(c[1]), "+f"(c[2]), "+f"(c[3])
        : "r"(a[0]), "r"(a[1]), "r"(a[2]), "r"(a[3]), "r"(b0), "r"(b1));
}
__device__ __forceinline__ uint32_t packbf(float a, float b){
    __nv_bfloat162 t = __floats2bfloat162_rn(a, b);
    return *(uint32_t*)&t;
}

// ---------------------------------------------------------------------------
// fp32 -> (bf16 hi, bf16 lo) split. which: 0=X, 1=Wqkv, 2=Wout
// ---------------------------------------------------------------------------
__global__ void __launch_bounds__(256)
split_convert(const float* __restrict__ src, int which, int n4)
{
    int i = blockIdx.x * 256 + threadIdx.x;
    if (i >= n4) return;
    __nv_bfloat16 *hi, *lo;
    if (which == 0)      { hi = g_Xhi; lo = g_Xlo; }
    else if (which == 1) { hi = g_Whi; lo = g_Wlo; }
    else                 { hi = g_Ohi; lo = g_Olo; }
    float4 v = ((const float4*)src)[i];
    __nv_bfloat16 h0 = __float2bfloat16(v.x);
    __nv_bfloat16 h1 = __float2bfloat16(v.y);
    __nv_bfloat16 h2 = __float2bfloat16(v.z);
    __nv_bfloat16 h3 = __float2bfloat16(v.w);
    __nv_bfloat16 l0 = __float2bfloat16(v.x - __bfloat162float(h0));
    __nv_bfloat16 l1 = __float2bfloat16(v.y - __bfloat162float(h1));
    __nv_bfloat16 l2 = __float2bfloat16(v.z - __bfloat162float(h2));
    __nv_bfloat16 l3 = __float2bfloat16(v.w - __bfloat162float(h3));
    ((__nv_bfloat162*)hi)[2*i]   = __halves2bfloat162(h0, h1);
    ((__nv_bfloat162*)hi)[2*i+1] = __halves2bfloat162(h2, h3);
    ((__nv_bfloat162*)lo)[2*i]   = __halves2bfloat162(l0, l1);
    ((__nv_bfloat162*)lo)[2*i+1] = __halves2bfloat162(l2, l3);
}

// ---------------------------------------------------------------------------
// Split-bf16 warp-MMA GEMM: C[m,n] = sum_k A[m,k]*B[n,k], K=1024.
// CTA tile 256x128, 8 warps (4m x 2n), warp tile 64x64, K chunk 64,
// 2-stage cp.async pipeline, XOR-swizzled rows.
// Pass-major MMA emission: per B-chunk, pass hh over all 8 accs, then hl,
// then lh -> same-accumulator reuse distance 8 (was 1) for HMMA ILP.
// ---------------------------------------------------------------------------
#define KC 64
#define A_ARR (256*128)                 // 256 rows x 128B = 32KB
#define B_ARR (128*128)                 // 128 rows x 128B = 16KB
#define STAGE_BYTES (2*A_ARR + 2*B_ARR) // 96KB
#define GEMM_SMEM (2*STAGE_BYTES)       // 192KB (epilogue reuses it)

__global__ void __launch_bounds__(256, 1)
gemm_split_kernel(float* __restrict__ Cout, int mode)
{
    char* sm = dynsm;
    const int tid = threadIdx.x;
    const int wid = tid >> 5, lane = tid & 31;
    const int m0 = blockIdx.y * 256;
    const int n0 = blockIdx.x * 128;

    const __nv_bfloat16 *Ahi, *Alo, *Bhi, *Blo;
    if (mode == 1) { Ahi = g_Xhi;  Alo = g_Xlo;  Bhi = g_Whi; Blo = g_Wlo; }
    else           { Ahi = g_AOhi; Alo = g_AOlo; Bhi = g_Ohi; Blo = g_Olo; }

    const uint32_t smb = smem_u32(sm);

    // warp layout: 4 (m) x 2 (n); warp tile 64x64
    const int wm0 = (wid >> 1) * 64;
    const int wn0 = (wid & 1) * 64;

    float acc[4][8][4];
#pragma unroll
    for (int a = 0; a < 4; a++)
#pragma unroll
        for (int b = 0; b < 8; b++)
#pragma unroll
            for (int c = 0; c < 4; c++) acc[a][b][c] = 0.f;

    // ---- global -> smem stage loader (cp.async, 24 x 16B per thread) ----
    auto load_stage = [&](int stage, int k0) {
        uint32_t sb = smb + stage * STAGE_BYTES;
#pragma unroll
        for (int c = 0; c < 8; c++) {
            int linear = c * 256 + tid;      // 0..2047
            int row = linear >> 3;           // 0..255
            int cb  = linear & 7;
            uint32_t off = row * 128 + ((cb ^ (row & 7)) << 4);
            const size_t g = (size_t)(m0 + row) * ND + k0 + cb * 8;
            cp16(sb + off,         Ahi + g);
            cp16(sb + A_ARR + off, Alo + g);
        }
#pragma unroll
        for (int c = 0; c < 4; c++) {
            int linear = c * 256 + tid;      // 0..1023
            int row = linear >> 3;           // 0..127
            int cb  = linear & 7;
            uint32_t off = row * 128 + ((cb ^ (row & 7)) << 4);
            const size_t g = (size_t)(n0 + row) * ND + k0 + cb * 8;
            cp16(sb + 2*A_ARR + off,         Bhi + g);
            cp16(sb + 2*A_ARR + B_ARR + off, Blo + g);
        }
        cp_commit();
    };

    load_stage(0, 0);

#pragma unroll 1
    for (int i = 0; i < 16; i++) {
        if (i < 15) load_stage((i + 1) & 1, (i + 1) * KC);
        if (i < 15) asm volatile("cp.async.wait_group 1;" ::: "memory");
        else        asm volatile("cp.async.wait_group 0;" ::: "memory");
        __syncthreads();

        uint32_t sb = smb + (i & 1) * STAGE_BYTES;
        uint32_t a_hi_b = sb, a_lo_b = sb + A_ARR;
        uint32_t b_hi_b = sb + 2*A_ARR, b_lo_b = sb + 2*A_ARR + B_ARR;

#pragma unroll
        for (int ks = 0; ks < 4; ks++) {
            // A fragments: 4 m16 tiles, hi+lo
            uint32_t ah[4][4], al[4][4];
            {
                int row = (lane & 15);
                int kb  = ks * 2 + (lane >> 4);
#pragma unroll
                for (int mt = 0; mt < 4; mt++) {
                    int r = wm0 + mt * 16 + row;
                    uint32_t off = r * 128 + (((uint32_t)(kb ^ (r & 7))) << 4);
                    ldsm_x4(ah[mt], a_hi_b + off);
                    ldsm_x4(al[mt], a_lo_b + off);
                }
            }
            // B in 4 chunks of 2 n8-tiles; pass-major over 8 accs per chunk
            int g = lane >> 3, trow = lane & 7;
#pragma unroll
            for (int p = 0; p < 4; p++) {
                int nrow = wn0 + (p * 2 + (g >> 1)) * 8 + trow;
                int kb = ks * 2 + (g & 1);
                uint32_t off = nrow * 128 + (((uint32_t)(kb ^ (nrow & 7))) << 4);
                uint32_t bh[4], bl[4];
                ldsm_x4(bh, b_hi_b + off);
                ldsm_x4(bl, b_lo_b + off);
                // pass 1: Ahi x Bhi over all 8 accumulators
#pragma unroll
                for (int mt = 0; mt < 4; mt++) {
                    mma_bf16(acc[mt][p*2],   ah[mt], bh[0], bh[1]);
                    mma_bf16(acc[mt][p*2+1], ah[mt], bh[2], bh[3]);
                }
                // pass 2: Ahi x Blo
#pragma unroll
                for (int mt = 0; mt < 4; mt++) {
                    mma_bf16(acc[mt][p*2],   ah[mt], bl[0], bl[1]);
                    mma_bf16(acc[mt][p*2+1], ah[mt], bl[2], bl[3]);
                }
                // pass 3: Alo x Bhi
#pragma unroll
                for (int mt = 0; mt < 4; mt++) {
                    mma_bf16(acc[mt][p*2],   al[mt], bh[0], bh[1]);
                    mma_bf16(acc[mt][p*2+1], al[mt], bh[2], bh[3]);
                }
            }
        }
        __syncthreads();
    }

    // ---- epilogue: acc -> smem (256x132 f32) -> vectorized global ----
    float* sf = (float*)sm;
    const int gq = lane >> 2, tq = lane & 3;
#pragma unroll
    for (int mt = 0; mt < 4; mt++)
#pragma unroll
        for (int nt = 0; nt < 8; nt++) {
            int m = wm0 + mt * 16 + gq;
            int n = wn0 + nt * 8 + 2 * tq;
            sf[m * 132 + n]           = acc[mt][nt][0];
            sf[m * 132 + n + 1]       = acc[mt][nt][1];
            sf[(m + 8) * 132 + n]     = acc[mt][nt][2];
            sf[(m + 8) * 132 + n + 1] = acc[mt][nt][3];
        }
    __syncthreads();

    // each thread: 16 consecutive cols of one row per pass, 8 passes
    const int rr  = tid >> 3;          // 0..31
    const int colg = (tid & 7) * 16;   // 0,16,...,112
#pragma unroll 1
    for (int pass = 0; pass < 8; pass++) {
        int r = pass * 32 + rr;
        const float* src = &sf[r * 132 + colg];
        if (mode == 0) {
            float4* dst = (float4*)&Cout[(size_t)(m0 + r) * ND + n0 + colg];
#pragma unroll
            for (int j = 0; j < 4; j++) dst[j] = ((const float4*)src)[j];
        } else {
            int col0 = n0 + colg;
            int part = col0 >> 10;
            int rem  = col0 & 1023;
            int h    = rem >> 6;
            int d0   = rem & 63;
            __nv_bfloat16 *dhi, *dlo;
            if (part == 0)      { dhi = g_Qhi; dlo = g_Qlo; }
            else if (part == 1) { dhi = g_Khi; dlo = g_Klo; }
            else                { dhi = g_Vhi; dlo = g_Vlo; }
            int m = m0 + r;
            int b = m >> 11, s = m & 2047;
            size_t base = (((size_t)(b * NH + h)) * NS + s) * NDK + d0;
            uint32_t hp[8], lp[8];
#pragma unroll
            for (int j = 0; j < 8; j++) {
                float v0 = src[2*j], v1 = src[2*j+1];
                float h0 = __bfloat162float(__float2bfloat16(v0));
                float h1 = __bfloat162float(__float2bfloat16(v1));
                hp[j] = packbf(v0, v1);
                lp[j] = packbf(v0 - h0, v1 - h1);
            }
            ((uint4*)&dhi[base])[0] = make_uint4(hp[0], hp[1], hp[2], hp[3]);
            ((uint4*)&dhi[base])[1] = make_uint4(hp[4], hp[5], hp[6], hp[7]);
            ((uint4*)&dlo[base])[0] = make_uint4(lp[0], lp[1], lp[2], lp[3]);
            ((uint4*)&dlo[base])[1] = make_uint4(lp[4], lp[5], lp[6], lp[7]);
        }
    }
}

// ---------------------------------------------------------------------------
// Stage 2: causal flash attention on mma.sync, split-bf16 throughout.
// BQ=128 (8 warps x 16 rows), BK=64, double-buffered K/V via cp.async.
// Pass-major MMA emission in QK and interleaved o0/o1 in PV for ILP.
// grid = (16 qtiles [reversed], 32 bh)
// ---------------------------------------------------------------------------
#define BQ 128
#define ATTN_SMEM_B (32768 + 2*32768)   // Q hi/lo 32KB + 2 stages x (K/V hi/lo 32KB)

__global__ void __launch_bounds__(256, 1)
attn_mma_kernel()
{
    const uint32_t smb = smem_u32(dynsm);
    const int tid = threadIdx.x;
    const int wid = tid >> 5, lane = tid & 31;
    const int qb = 15 - (int)blockIdx.x;      // biggest q-tiles first
    const int bh = blockIdx.y;
    const int q0 = qb * BQ;
    const int nkt = 2*qb + 2;

    const size_t bho = (size_t)bh * NS * NDK;
    const __nv_bfloat16* Qhg = g_Qhi + bho;
    const __nv_bfloat16* Qlg = g_Qlo + bho;
    const __nv_bfloat16* Khg = g_Khi + bho;
    const __nv_bfloat16* Klg = g_Klo + bho;
    const __nv_bfloat16* Vhg = g_Vhi + bho;
    const __nv_bfloat16* Vlg = g_Vlo + bho;

    // prologue: Q tile (128 x 64 hi/lo) -> smem [row][d] swizzled
#pragma unroll
    for (int c = 0; c < 4; c++) {
        int linear = c*256 + tid;
        int row = linear >> 3, cb = linear & 7;
        uint32_t sa = smb + row*128 + ((cb ^ (row & 7)) << 4);
        cp16(sa,         Qhg + (size_t)(q0 + row)*NDK + cb*8);
        cp16(sa + 16384, Qlg + (size_t)(q0 + row)*NDK + cb*8);
    }
    auto load_stage = [&](int stage, int k0){
        uint32_t sb = smb + 32768 + stage*32768;
        const __nv_bfloat16* srcs[4] = {Khg, Klg, Vhg, Vlg};
#pragma unroll
        for (int arr = 0; arr < 4; arr++) {
#pragma unroll
            for (int c = 0; c < 2; c++) {
                int linear = c*256 + tid;
                int row = linear >> 3, cb = linear & 7;
                uint32_t sa = sb + arr*8192 + row*128 + ((cb ^ (row & 7)) << 4);
                cp16(sa, srcs[arr] + (size_t)(k0 + row)*NDK + cb*8);
            }
        }
        cp_commit();
    };
    load_stage(0, 0);
    asm volatile("cp.async.wait_group 0;" ::: "memory");
    __syncthreads();

    uint32_t qh[4][4], ql[4][4];
    {
        int r = wid*16 + (lane & 15);
#pragma unroll
        for (int ks = 0; ks < 4; ks++) {
            int cb = ks*2 + (lane >> 4);
            uint32_t off = r*128 + (((uint32_t)(cb ^ (r & 7))) << 4);
            ldsm_x4(qh[ks], smb + off);
            ldsm_x4(ql[ks], smb + 16384 + off);
        }
    }

    float o[8][4];
#pragma unroll
    for (int nt = 0; nt < 8; nt++)
#pragma unroll
        for (int f = 0; f < 4; f++) o[nt][f] = 0.f;
    float mrow[2] = {-INFINITY, -INFINITY};
    float lrow[2] = {0.f, 0.f};

#pragma unroll 1
    for (int kt = 0; kt < nkt; kt++) {
        if (kt + 1 < nkt) {
            load_stage((kt + 1) & 1, (kt + 1) * 64);
            asm volatile("cp.async.wait_group 1;" ::: "memory");
        } else {
            asm volatile("cp.async.wait_group 0;" ::: "memory");
        }
        __syncthreads();
        uint32_t sb = smb + 32768 + (kt & 1)*32768;

        // ---- S = Q.K^T (split, pass-major over 4 accs), 16x64 per warp ----
        float s[8][4];
#pragma unroll
        for (int nt = 0; nt < 8; nt++)
#pragma unroll
            for (int f = 0; f < 4; f++) s[nt][f] = 0.f;

#pragma unroll
        for (int ks = 0; ks < 4; ks++) {
#pragma unroll
            for (int half = 0; half < 2; half++) {
                uint32_t kh4[4][2], kl4[4][2];
                int g = lane >> 3, trow = lane & 7;
#pragma unroll
                for (int p = 0; p < 2; p++) {
                    int nrow = half*32 + (p*2 + (g >> 1))*8 + trow;
                    int kb = ks*2 + (g & 1);
                    uint32_t off = nrow*128 + (((uint32_t)(kb ^ (nrow & 7))) << 4);
                    uint32_t r4[4];
                    ldsm_x4(r4, sb + off);
                    kh4[p*2][0] = r4[0]; kh4[p*2][1] = r4[1];
                    kh4[p*2+1][0] = r4[2]; kh4[p*2+1][1] = r4[3];
                    ldsm_x4(r4, sb + 8192 + off);
                    kl4[p*2][0] = r4[0]; kl4[p*2][1] = r4[1];
                    kl4[p*2+1][0] = r4[2]; kl4[p*2+1][1] = r4[3];
                }
                // pass-major: hh over 4 accs, then hl, then lh
#pragma unroll
                for (int nt = 0; nt < 4; nt++)
                    mma_bf16(s[half*4 + nt], qh[ks], kh4[nt][0], kh4[nt][1]);
#pragma unroll
                for (int nt = 0; nt < 4; nt++)
                    mma_bf16(s[half*4 + nt], qh[ks], kl4[nt][0], kl4[nt][1]);
#pragma unroll
                for (int nt = 0; nt < 4; nt++)
                    mma_bf16(s[half*4 + nt], ql[ks], kh4[nt][0], kh4[nt][1]);
            }
        }

        // ---- scale + causal mask ----
#pragma unroll
        for (int nt = 0; nt < 8; nt++)
#pragma unroll
            for (int f = 0; f < 4; f++) s[nt][f] *= 0.125f;
        if (kt >= nkt - 2) {
            int lim0 = q0 + wid*16 + (lane >> 2) - kt*64;
#pragma unroll
            for (int nt = 0; nt < 8; nt++) {
                int cb = nt*8 + (lane & 3)*2;
                if (cb     > lim0)     s[nt][0] = -INFINITY;
                if (cb + 1 > lim0)     s[nt][1] = -INFINITY;
                if (cb     > lim0 + 8) s[nt][2] = -INFINITY;
                if (cb + 1 > lim0 + 8) s[nt][3] = -INFINITY;
            }
        }

        // ---- online softmax in fragments; pack P hi/lo ----
        uint32_t phi[8][2], plo[8][2];
#pragma unroll
        for (int rh = 0; rh < 2; rh++) {
            float tm = -INFINITY;
#pragma unroll
            for (int nt = 0; nt < 8; nt++)
                tm = fmaxf(tm, fmaxf(s[nt][2*rh], s[nt][2*rh+1]));
            tm = fmaxf(tm, __shfl_xor_sync(0xffffffffu, tm, 1));
            tm = fmaxf(tm, __shfl_xor_sync(0xffffffffu, tm, 2));
            float mn  = fmaxf(mrow[rh], tm);
            float sc  = __expf(mrow[rh] - mn);
            float sum = 0.f;
#pragma unroll
            for (int nt = 0; nt < 8; nt++) {
                float p0 = __expf(s[nt][2*rh]     - mn);
                float p1 = __expf(s[nt][2*rh + 1] - mn);
                sum += p0 + p1;
                float h0 = __bfloat162float(__float2bfloat16(p0));
                float h1 = __bfloat162float(__float2bfloat16(p1));
                phi[nt][rh] = packbf(p0, p1);
                plo[nt][rh] = packbf(p0 - h0, p1 - h1);
            }
            sum += __shfl_xor_sync(0xffffffffu, sum, 1);
            sum += __shfl_xor_sync(0xffffffffu, sum, 2);
            lrow[rh] = lrow[rh]*sc + sum;
            mrow[rh] = mn;
#pragma unroll
            for (int nt = 0; nt < 8; nt++) {
                o[nt][2*rh]     *= sc;
                o[nt][2*rh + 1] *= sc;
            }
        }

        // ---- O += P.V (split, o0/o1 interleaved), V via ldmatrix.trans ----
#pragma unroll
        for (int ks = 0; ks < 4; ks++) {
            uint32_t aph[4] = {phi[2*ks][0], phi[2*ks][1], phi[2*ks+1][0], phi[2*ks+1][1]};
            uint32_t apl[4] = {plo[2*ks][0], plo[2*ks][1], plo[2*ks+1][0], plo[2*ks+1][1]};
#pragma unroll
            for (int dh = 0; dh < 4; dh++) {
                int r  = 16*ks + (lane & 15);
                int cb = dh*2 + (lane >> 4);
                uint32_t off = r*128 + (((uint32_t)(cb ^ (r & 7))) << 4);
                uint32_t vh[4], vl[4];
                ldsm_x4_t(vh, sb + 16384 + off);
                ldsm_x4_t(vl, sb + 24576 + off);
                // interleave the two accumulators between same-acc reuses
                mma_bf16(o[dh*2],   aph, vh[0], vh[1]);
                mma_bf16(o[dh*2+1], aph, vh[2], vh[3]);
                mma_bf16(o[dh*2],   aph, vl[0], vl[1]);
                mma_bf16(o[dh*2+1], aph, vl[2], vl[3]);
                mma_bf16(o[dh*2],   apl, vh[0], vh[1]);
                mma_bf16(o[dh*2+1], apl, vh[2], vh[3]);
            }
        }
        __syncthreads();
    }

    // ---- epilogue: O / l -> split bf16 hi/lo at [b*s][h*dk] ----
    const int b = bh >> 4, h = bh & 15;
#pragma unroll
    for (int rh = 0; rh < 2; rh++) {
        float inv = 1.0f / lrow[rh];
        int qrow = q0 + wid*16 + (lane >> 2) + rh*8;
        size_t rowbase = ((size_t)(b*NS + qrow))*ND + h*NDK;
#pragma unroll
        for (int nt = 0; nt < 8; nt++) {
            float v0 = o[nt][2*rh]     * inv;
            float v1 = o[nt][2*rh + 1] * inv;
            size_t idx = rowbase + nt*8 + (lane & 3)*2;
            float h0 = __bfloat162float(__float2bfloat16(v0));
            float h1 = __bfloat162float(__float2bfloat16(v1));
            *(uint32_t*)&g_AOhi[idx] = packbf(v0, v1);
            *(uint32_t*)&g_AOlo[idx] = packbf(v0 - h0, v1 - h1);
        }
    }
}

// ---------------------------------------------------------------------------

extern "C" void kernel_launch(void* const* d_in, const int* in_sizes, int n_in,
                              void* d_out, int out_size)
{
    const float* X    = (const float*)d_in[0];   // [2,2048,1024]
    const float* Wqkv = (const float*)d_in[1];   // [3072,1024]
    const float* Wout = (const float*)d_in[2];   // [1024,1024]
    float* out = (float*)d_out;                  // [2,2048,1024]

    cudaFuncSetAttribute(gemm_split_kernel, cudaFuncAttributeMaxDynamicSharedMemorySize, GEMM_SMEM);
    cudaFuncSetAttribute(attn_mma_kernel,  cudaFuncAttributeMaxDynamicSharedMemorySize, ATTN_SMEM_B);

    split_convert<<<(MT*ND/4)/256,    256>>>(X,    0, MT*ND/4);
    split_convert<<<(QKV_N*ND/4)/256, 256>>>(Wqkv, 1, QKV_N*ND/4);
    split_convert<<<(ND*ND/4)/256,    256>>>(Wout, 2, ND*ND/4);

    gemm_split_kernel<<<dim3(QKV_N/128, MT/256), 256, GEMM_SMEM>>>(nullptr, 1);
    attn_mma_kernel<<<dim3(NS/BQ, NB*NH), 256, ATTN_SMEM_B>>>();
    gemm_split_kernel<<<dim3(ND/128, MT/256), 256, GEMM_SMEM>>>(out, 0);
}

// round 12
// speedup vs baseline: 1.1383x; 1.1189x over previous
#include <cuda_runtime.h>
#include <cuda_bf16.h>
#include <cuda_fp16.h>
#include <math.h>
#include <stdint.h>

#define NS 2048
#define NB 2
#define NH 16
#define NDK 64
#define ND 1024
#define MT (NB*NS)          // 4096 rows total
#define QKV_N (3*ND)        // 3072

// single dynamic-shared symbol for the whole TU (kernels cast as needed)
extern __shared__ char dynsm[];

// Scratch (allocation-free rule: __device__ globals)
__device__ __nv_bfloat16 g_Xhi[MT*ND];      // bf16 split (qkv GEMM operands)
__device__ __nv_bfloat16 g_Xlo[MT*ND];
__device__ __nv_bfloat16 g_Whi[QKV_N*ND];
__device__ __nv_bfloat16 g_Wlo[QKV_N*ND];
__device__ __half g_Ohi[ND*ND];             // fp16 split (outproj operands)
__device__ __half g_Olo[ND*ND];
__device__ __half g_AOhi[MT*ND];
__device__ __half g_AOlo[MT*ND];
__device__ __half g_Qhi[NB*NH*NS*NDK];      // [b][h][s][d] fp16
__device__ __half g_Qlo[NB*NH*NS*NDK];      // Q needs lo (A-operand of QK)
__device__ __half g_Khi[NB*NH*NS*NDK];      // K hi-only (B-operand)
__device__ __half g_Vhi[NB*NH*NS*NDK];      // V hi-only (B-operand)

// ---------------------------------------------------------------------------
// helpers (portable PTX only: mma.sync / ldmatrix / cp.async — no tcgen05)
// ---------------------------------------------------------------------------
__device__ __forceinline__ uint32_t smem_u32(const void* p){
    uint32_t a;
    asm("{ .reg .u64 t; cvta.to.shared.u64 t, %1; cvt.u32.u64 %0, t; }" : "=r"(a) : "l"(p));
    return a;
}
__device__ __forceinline__ void cp16(uint32_t saddr, const void* g){
    asm volatile("cp.async.cg.shared.global [%0], [%1], 16;" :: "r"(saddr), "l"(g));
}
__device__ __forceinline__ void cp_commit(){
    asm volatile("cp.async.commit_group;" ::: "memory");
}
__device__ __forceinline__ void ldsm_x4(uint32_t r[4], uint32_t addr){
    asm volatile("ldmatrix.sync.aligned.m8n8.x4.shared.b16 {%0,%1,%2,%3}, [%4];"
                 : "=r"(r[0]), "=r"(r[1]), "=r"(r[2]), "=r"(r[3]) : "r"(addr));
}
__device__ __forceinline__ void ldsm_x4_t(uint32_t r[4], uint32_t addr){
    asm volatile("ldmatrix.sync.aligned.m8n8.x4.trans.shared.b16 {%0,%1,%2,%3}, [%4];"
                 : "=r"(r[0]), "=r"(r[1]), "=r"(r[2]), "=r"(r[3]) : "r"(addr));
}
__device__ __forceinline__ void mma_bf16(float c[4], const uint32_t a[4],
                                         const uint32_t b0, const uint32_t b1){
    asm volatile(
        "mma.sync.aligned.m16n8k16.row.col.f32.bf16.bf16.f32 "
        "{%0,%1,%2,%3}, {%4,%5,%6,%7}, {%8,%9}, {%0,%1,%2,%3};"
        : "+f"(c[0]), "+f"(c[1]), "+f"(c[2]), "+f"(c[3])
        : "r"(a[0]), "r"(a[1]), "r"(a[2]), "r"(a[3]), "r"(b0), "r"(b1));
}
__device__ __forceinline__ void mma_f16(float c[4], const uint32_t a[4],
                                        const uint32_t b0, const uint32_t b1){
    asm volatile(
        "mma.sync.aligned.m16n8k16.row.col.f32.f16.f16.f32 "
        "{%0,%1,%2,%3}, {%4,%5,%6,%7}, {%8,%9}, {%0,%1,%2,%3};"
        : "+f"(c[0]), "+f"(c[1]), "+f"(c[2]), "+f"(c[3])
        : "r"(a[0]), "r"(a[1]), "r"(a[2]), "r"(a[3]), "r"(b0), "r"(b1));
}
__device__ __forceinline__ uint32_t packbf(float a, float b){
    __nv_bfloat162 t = __floats2bfloat162_rn(a, b);
    return *(uint32_t*)&t;
}
__device__ __forceinline__ uint32_t packh(float a, float b){
    __half2 t = __floats2half2_rn(a, b);
    return *(uint32_t*)&t;
}

// ---------------------------------------------------------------------------
// fp32 splits: which 0=X (bf16), 1=Wqkv (bf16), 2=Wout (fp16)
// ---------------------------------------------------------------------------
__global__ void __launch_bounds__(256)
split_convert(const float* __restrict__ src, int which, int n4)
{
    int i = blockIdx.x * 256 + threadIdx.x;
    if (i >= n4) return;
    float4 v = ((const float4*)src)[i];
    if (which == 2) {
        __half h0 = __float2half_rn(v.x), h1 = __float2half_rn(v.y);
        __half h2 = __float2half_rn(v.z), h3 = __float2half_rn(v.w);
        __half l0 = __float2half_rn(v.x - __half2float(h0));
        __half l1 = __float2half_rn(v.y - __half2float(h1));
        __half l2 = __float2half_rn(v.z - __half2float(h2));
        __half l3 = __float2half_rn(v.w - __half2float(h3));
        ((__half2*)g_Ohi)[2*i]   = __halves2half2(h0, h1);
        ((__half2*)g_Ohi)[2*i+1] = __halves2half2(h2, h3);
        ((__half2*)g_Olo)[2*i]   = __halves2half2(l0, l1);
        ((__half2*)g_Olo)[2*i+1] = __halves2half2(l2, l3);
        return;
    }
    __nv_bfloat16 *hi, *lo;
    if (which == 0) { hi = g_Xhi; lo = g_Xlo; }
    else            { hi = g_Whi; lo = g_Wlo; }
    __nv_bfloat16 h0 = __float2bfloat16(v.x);
    __nv_bfloat16 h1 = __float2bfloat16(v.y);
    __nv_bfloat16 h2 = __float2bfloat16(v.z);
    __nv_bfloat16 h3 = __float2bfloat16(v.w);
    __nv_bfloat16 l0 = __float2bfloat16(v.x - __bfloat162float(h0));
    __nv_bfloat16 l1 = __float2bfloat16(v.y - __bfloat162float(h1));
    __nv_bfloat16 l2 = __float2bfloat16(v.z - __bfloat162float(h2));
    __nv_bfloat16 l3 = __float2bfloat16(v.w - __bfloat162float(h3));
    ((__nv_bfloat162*)hi)[2*i]   = __halves2bfloat162(h0, h1);
    ((__nv_bfloat162*)hi)[2*i+1] = __halves2bfloat162(h2, h3);
    ((__nv_bfloat162*)lo)[2*i]   = __halves2bfloat162(l0, l1);
    ((__nv_bfloat162*)lo)[2*i+1] = __halves2bfloat162(l2, l3);
}

// ---------------------------------------------------------------------------
// Split warp-MMA GEMM (3-pass hh/hl/lh): C[m,n] = sum_k A[m,k]*B[n,k], K=1024.
// CTA tile 256x128, 8 warps (4m x 2n), warp tile 64x64, 2-stage cp.async.
// MODE 1: bf16, A=X, B=Wqkv  -> epilogue packs fp16: Q hi+lo, K hi, V hi.
// MODE 0: fp16, A=AO, B=Wout -> Cout fp32.
// ---------------------------------------------------------------------------
#define KC 64
#define A_ARR (256*128)                 // 256 rows x 128B = 32KB
#define B_ARR (128*128)                 // 128 rows x 128B = 16KB
#define STAGE_BYTES (2*A_ARR + 2*B_ARR) // 96KB
#define GEMM_SMEM (2*STAGE_BYTES)       // 192KB (epilogue reuses it)

template<int MODE>
__global__ void __launch_bounds__(256, 1)
gemm_split_kernel(float* __restrict__ Cout)
{
    char* sm = dynsm;
    const int tid = threadIdx.x;
    const int wid = tid >> 5, lane = tid & 31;
    const int m0 = blockIdx.y * 256;
    const int n0 = blockIdx.x * 128;

    // 2-byte element views (bf16 for MODE 1, fp16 for MODE 0)
    const uint16_t *Ahi, *Alo, *Bhi, *Blo;
    if (MODE == 1) {
        Ahi = (const uint16_t*)g_Xhi;  Alo = (const uint16_t*)g_Xlo;
        Bhi = (const uint16_t*)g_Whi;  Blo = (const uint16_t*)g_Wlo;
    } else {
        Ahi = (const uint16_t*)g_AOhi; Alo = (const uint16_t*)g_AOlo;
        Bhi = (const uint16_t*)g_Ohi;  Blo = (const uint16_t*)g_Olo;
    }

    auto MMA = [](float* c, const uint32_t* a, uint32_t b0, uint32_t b1){
        if (MODE == 1) mma_bf16(c, a, b0, b1);
        else           mma_f16(c, a, b0, b1);
    };

    const uint32_t smb = smem_u32(sm);

    const int wm0 = (wid >> 1) * 64;
    const int wn0 = (wid & 1) * 64;

    float acc[4][8][4];
#pragma unroll
    for (int a = 0; a < 4; a++)
#pragma unroll
        for (int b = 0; b < 8; b++)
#pragma unroll
            for (int c = 0; c < 4; c++) acc[a][b][c] = 0.f;

    auto load_stage = [&](int stage, int k0) {
        uint32_t sb = smb + stage * STAGE_BYTES;
#pragma unroll
        for (int c = 0; c < 8; c++) {
            int linear = c * 256 + tid;
            int row = linear >> 3;
            int cb  = linear & 7;
            uint32_t off = row * 128 + ((cb ^ (row & 7)) << 4);
            const size_t g = (size_t)(m0 + row) * ND + k0 + cb * 8;
            cp16(sb + off,         Ahi + g);
            cp16(sb + A_ARR + off, Alo + g);
        }
#pragma unroll
        for (int c = 0; c < 4; c++) {
            int linear = c * 256 + tid;
            int row = linear >> 3;
            int cb  = linear & 7;
            uint32_t off = row * 128 + ((cb ^ (row & 7)) << 4);
            const size_t g = (size_t)(n0 + row) * ND + k0 + cb * 8;
            cp16(sb + 2*A_ARR + off,         Bhi + g);
            cp16(sb + 2*A_ARR + B_ARR + off, Blo + g);
        }
        cp_commit();
    };

    load_stage(0, 0);

#pragma unroll 1
    for (int i = 0; i < 16; i++) {
        if (i < 15) load_stage((i + 1) & 1, (i + 1) * KC);
        if (i < 15) asm volatile("cp.async.wait_group 1;" ::: "memory");
        else        asm volatile("cp.async.wait_group 0;" ::: "memory");
        __syncthreads();

        uint32_t sb = smb + (i & 1) * STAGE_BYTES;
        uint32_t a_hi_b = sb, a_lo_b = sb + A_ARR;
        uint32_t b_hi_b = sb + 2*A_ARR, b_lo_b = sb + 2*A_ARR + B_ARR;

#pragma unroll
        for (int ks = 0; ks < 4; ks++) {
            uint32_t ah[4][4], al[4][4];
            {
                int row = (lane & 15);
                int kb  = ks * 2 + (lane >> 4);
#pragma unroll
                for (int mt = 0; mt < 4; mt++) {
                    int r = wm0 + mt * 16 + row;
                    uint32_t off = r * 128 + (((uint32_t)(kb ^ (r & 7))) << 4);
                    ldsm_x4(ah[mt], a_hi_b + off);
                    ldsm_x4(al[mt], a_lo_b + off);
                }
            }
            int g = lane >> 3, trow = lane & 7;
#pragma unroll
            for (int p = 0; p < 4; p++) {
                int nrow = wn0 + (p * 2 + (g >> 1)) * 8 + trow;
                int kb = ks * 2 + (g & 1);
                uint32_t off = nrow * 128 + (((uint32_t)(kb ^ (nrow & 7))) << 4);
                uint32_t bh[4], bl[4];
                ldsm_x4(bh, b_hi_b + off);
                ldsm_x4(bl, b_lo_b + off);
#pragma unroll
                for (int mt = 0; mt < 4; mt++) {
                    MMA(acc[mt][p*2],   ah[mt], bh[0], bh[1]);
                    MMA(acc[mt][p*2+1], ah[mt], bh[2], bh[3]);
                }
#pragma unroll
                for (int mt = 0; mt < 4; mt++) {
                    MMA(acc[mt][p*2],   ah[mt], bl[0], bl[1]);
                    MMA(acc[mt][p*2+1], ah[mt], bl[2], bl[3]);
                }
#pragma unroll
                for (int mt = 0; mt < 4; mt++) {
                    MMA(acc[mt][p*2],   al[mt], bh[0], bh[1]);
                    MMA(acc[mt][p*2+1], al[mt], bh[2], bh[3]);
                }
            }
        }
        __syncthreads();
    }

    // ---- epilogue: acc -> smem (256x132 f32) -> vectorized global ----
    float* sf = (float*)sm;
    const int gq = lane >> 2, tq = lane & 3;
#pragma unroll
    for (int mt = 0; mt < 4; mt++)
#pragma unroll
        for (int nt = 0; nt < 8; nt++) {
            int m = wm0 + mt * 16 + gq;
            int n = wn0 + nt * 8 + 2 * tq;
            sf[m * 132 + n]           = acc[mt][nt][0];
            sf[m * 132 + n + 1]       = acc[mt][nt][1];
            sf[(m + 8) * 132 + n]     = acc[mt][nt][2];
            sf[(m + 8) * 132 + n + 1] = acc[mt][nt][3];
        }
    __syncthreads();

    const int rr  = tid >> 3;
    const int colg = (tid & 7) * 16;
#pragma unroll 1
    for (int pass = 0; pass < 8; pass++) {
        int r = pass * 32 + rr;
        const float* src = &sf[r * 132 + colg];
        if (MODE == 0) {
            float4* dst = (float4*)&Cout[(size_t)(m0 + r) * ND + n0 + colg];
#pragma unroll
            for (int j = 0; j < 4; j++) dst[j] = ((const float4*)src)[j];
        } else {
            int col0 = n0 + colg;
            int part = col0 >> 10;
            int rem  = col0 & 1023;
            int h    = rem >> 6;
            int d0   = rem & 63;
            int m = m0 + r;
            int b = m >> 11, s = m & 2047;
            size_t base = (((size_t)(b * NH + h)) * NS + s) * NDK + d0;
            uint32_t hp[8], lp[8];
#pragma unroll
            for (int j = 0; j < 8; j++) {
                float v0 = src[2*j], v1 = src[2*j+1];
                float h0 = __half2float(__float2half_rn(v0));
                float h1 = __half2float(__float2half_rn(v1));
                hp[j] = packh(v0, v1);
                lp[j] = packh(v0 - h0, v1 - h1);
            }
            if (part == 0) {            // Q: hi + lo (A-operand of QK)
                ((uint4*)&g_Qhi[base])[0] = make_uint4(hp[0], hp[1], hp[2], hp[3]);
                ((uint4*)&g_Qhi[base])[1] = make_uint4(hp[4], hp[5], hp[6], hp[7]);
                ((uint4*)&g_Qlo[base])[0] = make_uint4(lp[0], lp[1], lp[2], lp[3]);
                ((uint4*)&g_Qlo[base])[1] = make_uint4(lp[4], lp[5], lp[6], lp[7]);
            } else if (part == 1) {     // K: hi only (B-operand)
                ((uint4*)&g_Khi[base])[0] = make_uint4(hp[0], hp[1], hp[2], hp[3]);
                ((uint4*)&g_Khi[base])[1] = make_uint4(hp[4], hp[5], hp[6], hp[7]);
            } else {                    // V: hi only (B-operand)
                ((uint4*)&g_Vhi[base])[0] = make_uint4(hp[0], hp[1], hp[2], hp[3]);
                ((uint4*)&g_Vhi[base])[1] = make_uint4(hp[4], hp[5], hp[6], hp[7]);
            }
        }
    }
}

// ---------------------------------------------------------------------------
// Stage 2: causal flash attention, fp16 2-pass mma.sync.
// Q (hi+lo) in registers; K hi-only, V hi-only double-buffered via cp.async.
// QK = (Qh+Ql).Kh  (2 passes);  PV = (Ph+Pl).Vh  (2 passes).
// BQ=128 (8 warps x 16 rows), BK=64; grid = (16 qtiles [reversed], 32 bh)
// ---------------------------------------------------------------------------
#define BQ 128
#define ATTN_STAGE 16384                // K hi 8KB + V hi 8KB
#define ATTN_SMEM_B (32768 + 2*ATTN_STAGE)   // Q hi/lo 32KB + 2 stages = 64KB

__global__ void __launch_bounds__(256, 1)
attn_mma_kernel()
{
    const uint32_t smb = smem_u32(dynsm);
    const int tid = threadIdx.x;
    const int wid = tid >> 5, lane = tid & 31;
    const int qb = 15 - (int)blockIdx.x;      // biggest q-tiles first
    const int bh = blockIdx.y;
    const int q0 = qb * BQ;
    const int nkt = 2*qb + 2;

    const size_t bho = (size_t)bh * NS * NDK;
    const __half* Qhg = g_Qhi + bho;
    const __half* Qlg = g_Qlo + bho;
    const __half* Khg = g_Khi + bho;
    const __half* Vhg = g_Vhi + bho;

    // prologue: Q tile (128 x 64 hi/lo) -> smem [row][d] swizzled
#pragma unroll
    for (int c = 0; c < 4; c++) {
        int linear = c*256 + tid;
        int row = linear >> 3, cb = linear & 7;
        uint32_t sa = smb + row*128 + ((cb ^ (row & 7)) << 4);
        cp16(sa,         Qhg + (size_t)(q0 + row)*NDK + cb*8);
        cp16(sa + 16384, Qlg + (size_t)(q0 + row)*NDK + cb*8);
    }
    auto load_stage = [&](int stage, int k0){
        uint32_t sb = smb + 32768 + stage*ATTN_STAGE;
#pragma unroll
        for (int c = 0; c < 2; c++) {
            int linear = c*256 + tid;
            int row = linear >> 3, cb = linear & 7;
            uint32_t off = row*128 + ((cb ^ (row & 7)) << 4);
            cp16(sb + off,        Khg + (size_t)(k0 + row)*NDK + cb*8);
            cp16(sb + 8192 + off, Vhg + (size_t)(k0 + row)*NDK + cb*8);
        }
        cp_commit();
    };
    load_stage(0, 0);
    asm volatile("cp.async.wait_group 0;" ::: "memory");
    __syncthreads();

    uint32_t qh[4][4], ql[4][4];
    {
        int r = wid*16 + (lane & 15);
#pragma unroll
        for (int ks = 0; ks < 4; ks++) {
            int cb = ks*2 + (lane >> 4);
            uint32_t off = r*128 + (((uint32_t)(cb ^ (r & 7))) << 4);
            ldsm_x4(qh[ks], smb + off);
            ldsm_x4(ql[ks], smb + 16384 + off);
        }
    }

    float o[8][4];
#pragma unroll
    for (int nt = 0; nt < 8; nt++)
#pragma unroll
        for (int f = 0; f < 4; f++) o[nt][f] = 0.f;
    float mrow[2] = {-INFINITY, -INFINITY};
    float lrow[2] = {0.f, 0.f};

#pragma unroll 1
    for (int kt = 0; kt < nkt; kt++) {
        if (kt + 1 < nkt) {
            load_stage((kt + 1) & 1, (kt + 1) * 64);
            asm volatile("cp.async.wait_group 1;" ::: "memory");
        } else {
            asm volatile("cp.async.wait_group 0;" ::: "memory");
        }
        __syncthreads();
        uint32_t sb = smb + 32768 + (kt & 1)*ATTN_STAGE;

        // ---- S = (Qh+Ql).Kh, 16x64 per warp ----
        float s[8][4];
#pragma unroll
        for (int nt = 0; nt < 8; nt++)
#pragma unroll
            for (int f = 0; f < 4; f++) s[nt][f] = 0.f;

#pragma unroll
        for (int ks = 0; ks < 4; ks++) {
#pragma unroll
            for (int half = 0; half < 2; half++) {
                uint32_t kh4[4][2];
                int g = lane >> 3, trow = lane & 7;
#pragma unroll
                for (int p = 0; p < 2; p++) {
                    int nrow = half*32 + (p*2 + (g >> 1))*8 + trow;
                    int kb = ks*2 + (g & 1);
                    uint32_t off = nrow*128 + (((uint32_t)(kb ^ (nrow & 7))) << 4);
                    uint32_t r4[4];
                    ldsm_x4(r4, sb + off);
                    kh4[p*2][0] = r4[0]; kh4[p*2][1] = r4[1];
                    kh4[p*2+1][0] = r4[2]; kh4[p*2+1][1] = r4[3];
                }
#pragma unroll
                for (int nt = 0; nt < 4; nt++)
                    mma_f16(s[half*4 + nt], qh[ks], kh4[nt][0], kh4[nt][1]);
#pragma unroll
                for (int nt = 0; nt < 4; nt++)
                    mma_f16(s[half*4 + nt], ql[ks], kh4[nt][0], kh4[nt][1]);
            }
        }

        // ---- scale + causal mask ----
#pragma unroll
        for (int nt = 0; nt < 8; nt++)
#pragma unroll
            for (int f = 0; f < 4; f++) s[nt][f] *= 0.125f;
        if (kt >= nkt - 2) {
            int lim0 = q0 + wid*16 + (lane >> 2) - kt*64;
#pragma unroll
            for (int nt = 0; nt < 8; nt++) {
                int cb = nt*8 + (lane & 3)*2;
                if (cb     > lim0)     s[nt][0] = -INFINITY;
                if (cb + 1 > lim0)     s[nt][1] = -INFINITY;
                if (cb     > lim0 + 8) s[nt][2] = -INFINITY;
                if (cb + 1 > lim0 + 8) s[nt][3] = -INFINITY;
            }
        }

        // ---- online softmax in fragments; pack P hi/lo (fp16) ----
        uint32_t phi[8][2], plo[8][2];
#pragma unroll
        for (int rh = 0; rh < 2; rh++) {
            float tm = -INFINITY;
#pragma unroll
            for (int nt = 0; nt < 8; nt++)
                tm = fmaxf(tm, fmaxf(s[nt][2*rh], s[nt][2*rh+1]));
            tm = fmaxf(tm, __shfl_xor_sync(0xffffffffu, tm, 1));
            tm = fmaxf(tm, __shfl_xor_sync(0xffffffffu, tm, 2));
            float mn  = fmaxf(mrow[rh], tm);
            float sc  = __expf(mrow[rh] - mn);
            float sum = 0.f;
#pragma unroll
            for (int nt = 0; nt < 8; nt++) {
                float p0 = __expf(s[nt][2*rh]     - mn);
                float p1 = __expf(s[nt][2*rh + 1] - mn);
                sum += p0 + p1;
                float h0 = __half2float(__float2half_rn(p0));
                float h1 = __half2float(__float2half_rn(p1));
                phi[nt][rh] = packh(p0, p1);
                plo[nt][rh] = packh(p0 - h0, p1 - h1);
            }
            sum += __shfl_xor_sync(0xffffffffu, sum, 1);
            sum += __shfl_xor_sync(0xffffffffu, sum, 2);
            lrow[rh] = lrow[rh]*sc + sum;
            mrow[rh] = mn;
#pragma unroll
            for (int nt = 0; nt < 8; nt++) {
                o[nt][2*rh]     *= sc;
                o[nt][2*rh + 1] *= sc;
            }
        }

        // ---- O += (Ph+Pl).Vh, V via ldmatrix.trans on [key][d] ----
#pragma unroll
        for (int ks = 0; ks < 4; ks++) {
            uint32_t aph[4] = {phi[2*ks][0], phi[2*ks][1], phi[2*ks+1][0], phi[2*ks+1][1]};
            uint32_t apl[4] = {plo[2*ks][0], plo[2*ks][1], plo[2*ks+1][0], plo[2*ks+1][1]};
#pragma unroll
            for (int dh = 0; dh < 4; dh++) {
                int r  = 16*ks + (lane & 15);
                int cb = dh*2 + (lane >> 4);
                uint32_t off = r*128 + (((uint32_t)(cb ^ (r & 7))) << 4);
                uint32_t vh[4];
                ldsm_x4_t(vh, sb + 8192 + off);
                mma_f16(o[dh*2],   aph, vh[0], vh[1]);
                mma_f16(o[dh*2+1], aph, vh[2], vh[3]);
                mma_f16(o[dh*2],   apl, vh[0], vh[1]);
                mma_f16(o[dh*2+1], apl, vh[2], vh[3]);
            }
        }
        __syncthreads();
    }

    // ---- epilogue: O / l -> fp16 hi/lo at [b*s][h*dk] ----
    const int b = bh >> 4, h = bh & 15;
#pragma unroll
    for (int rh = 0; rh < 2; rh++) {
        float inv = 1.0f / lrow[rh];
        int qrow = q0 + wid*16 + (lane >> 2) + rh*8;
        size_t rowbase = ((size_t)(b*NS + qrow))*ND + h*NDK;
#pragma unroll
        for (int nt = 0; nt < 8; nt++) {
            float v0 = o[nt][2*rh]     * inv;
            float v1 = o[nt][2*rh + 1] * inv;
            size_t idx = rowbase + nt*8 + (lane & 3)*2;
            float h0 = __half2float(__float2half_rn(v0));
            float h1 = __half2float(__float2half_rn(v1));
            *(uint32_t*)&g_AOhi[idx] = packh(v0, v1);
            *(uint32_t*)&g_AOlo[idx] = packh(v0 - h0, v1 - h1);
        }
    }
}

// ---------------------------------------------------------------------------

extern "C" void kernel_launch(void* const* d_in, const int* in_sizes, int n_in,
                              void* d_out, int out_size)
{
    const float* X    = (const float*)d_in[0];   // [2,2048,1024]
    const float* Wqkv = (const float*)d_in[1];   // [3072,1024]
    const float* Wout = (const float*)d_in[2];   // [1024,1024]
    float* out = (float*)d_out;                  // [2,2048,1024]

    cudaFuncSetAttribute(gemm_split_kernel<1>, cudaFuncAttributeMaxDynamicSharedMemorySize, GEMM_SMEM);
    cudaFuncSetAttribute(gemm_split_kernel<0>, cudaFuncAttributeMaxDynamicSharedMemorySize, GEMM_SMEM);
    cudaFuncSetAttribute(attn_mma_kernel,      cudaFuncAttributeMaxDynamicSharedMemorySize, ATTN_SMEM_B);

    split_convert<<<(MT*ND/4)/256,    256>>>(X,    0, MT*ND/4);
    split_convert<<<(QKV_N*ND/4)/256, 256>>>(Wqkv, 1, QKV_N*ND/4);
    split_convert<<<(ND*ND/4)/256,    256>>>(Wout, 2, ND*ND/4);

    gemm_split_kernel<1><<<dim3(QKV_N/128, MT/256), 256, GEMM_SMEM>>>(nullptr);
    attn_mma_kernel<<<dim3(NS/BQ, NB*NH), 256, ATTN_SMEM_B>>>();
    gemm_split_kernel<0><<<dim3(ND/128, MT/256), 256, GEMM_SMEM>>>(out);
}

// round 15
// speedup vs baseline: 1.3894x; 1.2205x over previous
#include <cuda_runtime.h>
#include <cuda_bf16.h>
#include <cuda_fp16.h>
#include <math.h>
#include <stdint.h>

#define NS 2048
#define NB 2
#define NH 16
#define NDK 64
#define ND 1024
#define MT (NB*NS)          // 4096 rows total
#define QKV_N (3*ND)        // 3072

// single dynamic-shared symbol for the whole TU (kernels cast as needed)
extern __shared__ char dynsm[];

// Scratch (allocation-free rule: __device__ globals) — all fp16 now
__device__ __half g_Xhi[MT*ND];             // X split hi/lo (A of qkv GEMM)
__device__ __half g_Xlo[MT*ND];
__device__ __half g_Whi[QKV_N*ND];          // Wqkv hi-only (B)
__device__ __half g_Ohi[ND*ND];             // Wout hi-only (B)
__device__ __half g_AOhi[MT*ND];            // attn out split hi/lo (A of outproj)
__device__ __half g_AOlo[MT*ND];
__device__ __half g_Qhi[NB*NH*NS*NDK];      // [b][h][s][d]
__device__ __half g_Qlo[NB*NH*NS*NDK];      // Q hi+lo (A of QK)
__device__ __half g_Khi[NB*NH*NS*NDK];      // K hi-only (B)
__device__ __half g_Vhi[NB*NH*NS*NDK];      // V hi-only (B)

// ---------------------------------------------------------------------------
// helpers (portable PTX only: mma.sync / ldmatrix / cp.async — no tcgen05)
// ---------------------------------------------------------------------------
__device__ __forceinline__ uint32_t smem_u32(const void* p){
    uint32_t a;
    asm("{ .reg .u64 t; cvta.to.shared.u64 t, %1; cvt.u32.u64 %0, t; }" : "=r"(a) : "l"(p));
    return a;
}
__device__ __forceinline__ void cp16(uint32_t saddr, const void* g){
    asm volatile("cp.async.cg.shared.global [%0], [%1], 16;" :: "r"(saddr), "l"(g));
}
__device__ __forceinline__ void cp_commit(){
    asm volatile("cp.async.commit_group;" ::: "memory");
}
__device__ __forceinline__ void ldsm_x4(uint32_t r[4], uint32_t addr){
    asm volatile("ldmatrix.sync.aligned.m8n8.x4.shared.b16 {%0,%1,%2,%3}, [%4];"
                 : "=r"(r[0]), "=r"(r[1]), "=r"(r[2]), "=r"(r[3]) : "r"(addr));
}
__device__ __forceinline__ void ldsm_x4_t(uint32_t r[4], uint32_t addr){
    asm volatile("ldmatrix.sync.aligned.m8n8.x4.trans.shared.b16 {%0,%1,%2,%3}, [%4];"
                 : "=r"(r[0]), "=r"(r[1]), "=r"(r[2]), "=r"(r[3]) : "r"(addr));
}
__device__ __forceinline__ void mma_f16(float c[4], const uint32_t a[4],
                                        const uint32_t b0, const uint32_t b1){
    asm volatile(
        "mma.sync.aligned.m16n8k16.row.col.f32.f16.f16.f32 "
        "{%0,%1,%2,%3}, {%4,%5,%6,%7}, {%8,%9}, {%0,%1,%2,%3};"
        : "+f"(c[0]), "+f"(c[1]), "+f"(c[2]), "+f"(c[3])
        : "r"(a[0]), "r"(a[1]), "r"(a[2]), "r"(a[3]), "r"(b0), "r"(b1));
}
__device__ __forceinline__ uint32_t packh(float a, float b){
    __half2 t = __floats2half2_rn(a, b);
    return *(uint32_t*)&t;
}

// ---------------------------------------------------------------------------
// fp32 -> fp16 splits: which 0=X (hi+lo), 1=Wqkv (hi), 2=Wout (hi)
// ---------------------------------------------------------------------------
__global__ void __launch_bounds__(256)
split_convert(const float* __restrict__ src, int which, int n4)
{
    int i = blockIdx.x * 256 + threadIdx.x;
    if (i >= n4) return;
    float4 v = ((const float4*)src)[i];
    __half h0 = __float2half_rn(v.x), h1 = __float2half_rn(v.y);
    __half h2 = __float2half_rn(v.z), h3 = __float2half_rn(v.w);
    if (which == 0) {
        __half l0 = __float2half_rn(v.x - __half2float(h0));
        __half l1 = __float2half_rn(v.y - __half2float(h1));
        __half l2 = __float2half_rn(v.z - __half2float(h2));
        __half l3 = __float2half_rn(v.w - __half2float(h3));
        ((__half2*)g_Xhi)[2*i]   = __halves2half2(h0, h1);
        ((__half2*)g_Xhi)[2*i+1] = __halves2half2(h2, h3);
        ((__half2*)g_Xlo)[2*i]   = __halves2half2(l0, l1);
        ((__half2*)g_Xlo)[2*i+1] = __halves2half2(l2, l3);
    } else {
        __half* hi = (which == 1) ? g_Whi : g_Ohi;
        ((__half2*)hi)[2*i]   = __halves2half2(h0, h1);
        ((__half2*)hi)[2*i+1] = __halves2half2(h2, h3);
    }
}

// ---------------------------------------------------------------------------
// 2-pass fp16 warp-MMA GEMM: C = (Ahi+Alo).Bhi, K=1024.
// CTA tile 256x128, 8 warps (4m x 2n), warp tile 64x64, 2-stage cp.async.
// MODE 1: A=X, B=Wqkv  -> epilogue packs fp16: Q hi+lo, K hi, V hi.
// MODE 0: A=AO, B=Wout -> Cout fp32.
// ---------------------------------------------------------------------------
#define KC 64
#define A_ARR (256*128)                 // 256 rows x 128B = 32KB
#define B_ARR (128*128)                 // 128 rows x 128B = 16KB
#define STAGE_BYTES (2*A_ARR + B_ARR)   // 80KB (Ahi, Alo, Bhi)
#define GEMM_SMEM (2*STAGE_BYTES)       // 160KB (epilogue reuses it)

template<int MODE>
__global__ void __launch_bounds__(256, 1)
gemm_split_kernel(float* __restrict__ Cout)
{
    char* sm = dynsm;
    const int tid = threadIdx.x;
    const int wid = tid >> 5, lane = tid & 31;
    const int m0 = blockIdx.y * 256;
    const int n0 = blockIdx.x * 128;

    const __half *Ahi, *Alo, *Bhi;
    if (MODE == 1) { Ahi = g_Xhi;  Alo = g_Xlo;  Bhi = g_Whi; }
    else           { Ahi = g_AOhi; Alo = g_AOlo; Bhi = g_Ohi; }

    const uint32_t smb = smem_u32(sm);

    const int wm0 = (wid >> 1) * 64;
    const int wn0 = (wid & 1) * 64;

    float acc[4][8][4];
#pragma unroll
    for (int a = 0; a < 4; a++)
#pragma unroll
        for (int b = 0; b < 8; b++)
#pragma unroll
            for (int c = 0; c < 4; c++) acc[a][b][c] = 0.f;

    auto load_stage = [&](int stage, int k0) {
        uint32_t sb = smb + stage * STAGE_BYTES;
#pragma unroll
        for (int c = 0; c < 8; c++) {
            int linear = c * 256 + tid;
            int row = linear >> 3;
            int cb  = linear & 7;
            uint32_t off = row * 128 + ((cb ^ (row & 7)) << 4);
            const size_t g = (size_t)(m0 + row) * ND + k0 + cb * 8;
            cp16(sb + off,         Ahi + g);
            cp16(sb + A_ARR + off, Alo + g);
        }
#pragma unroll
        for (int c = 0; c < 4; c++) {
            int linear = c * 256 + tid;
            int row = linear >> 3;
            int cb  = linear & 7;
            uint32_t off = row * 128 + ((cb ^ (row & 7)) << 4);
            cp16(sb + 2*A_ARR + off, Bhi + (size_t)(n0 + row) * ND + k0 + cb * 8);
        }
        cp_commit();
    };

    load_stage(0, 0);

#pragma unroll 1
    for (int i = 0; i < 16; i++) {
        if (i < 15) load_stage((i + 1) & 1, (i + 1) * KC);
        if (i < 15) asm volatile("cp.async.wait_group 1;" ::: "memory");
        else        asm volatile("cp.async.wait_group 0;" ::: "memory");
        __syncthreads();

        uint32_t sb = smb + (i & 1) * STAGE_BYTES;
        uint32_t a_hi_b = sb, a_lo_b = sb + A_ARR;
        uint32_t b_hi_b = sb + 2*A_ARR;

#pragma unroll
        for (int ks = 0; ks < 4; ks++) {
            uint32_t ah[4][4], al[4][4];
            {
                int row = (lane & 15);
                int kb  = ks * 2 + (lane >> 4);
#pragma unroll
                for (int mt = 0; mt < 4; mt++) {
                    int r = wm0 + mt * 16 + row;
                    uint32_t off = r * 128 + (((uint32_t)(kb ^ (r & 7))) << 4);
                    ldsm_x4(ah[mt], a_hi_b + off);
                    ldsm_x4(al[mt], a_lo_b + off);
                }
            }
            int g = lane >> 3, trow = lane & 7;
#pragma unroll
            for (int p = 0; p < 4; p++) {
                int nrow = wn0 + (p * 2 + (g >> 1)) * 8 + trow;
                int kb = ks * 2 + (g & 1);
                uint32_t off = nrow * 128 + (((uint32_t)(kb ^ (nrow & 7))) << 4);
                uint32_t bh[4];
                ldsm_x4(bh, b_hi_b + off);
#pragma unroll
                for (int mt = 0; mt < 4; mt++) {
                    mma_f16(acc[mt][p*2],   ah[mt], bh[0], bh[1]);
                    mma_f16(acc[mt][p*2+1], ah[mt], bh[2], bh[3]);
                }
#pragma unroll
                for (int mt = 0; mt < 4; mt++) {
                    mma_f16(acc[mt][p*2],   al[mt], bh[0], bh[1]);
                    mma_f16(acc[mt][p*2+1], al[mt], bh[2], bh[3]);
                }
            }
        }
        __syncthreads();
    }

    // ---- epilogue: acc -> smem (256x132 f32) -> vectorized global ----
    float* sf = (float*)sm;
    const int gq = lane >> 2, tq = lane & 3;
#pragma unroll
    for (int mt = 0; mt < 4; mt++)
#pragma unroll
        for (int nt = 0; nt < 8; nt++) {
            int m = wm0 + mt * 16 + gq;
            int n = wn0 + nt * 8 + 2 * tq;
            sf[m * 132 + n]           = acc[mt][nt][0];
            sf[m * 132 + n + 1]       = acc[mt][nt][1];
            sf[(m + 8) * 132 + n]     = acc[mt][nt][2];
            sf[(m + 8) * 132 + n + 1] = acc[mt][nt][3];
        }
    __syncthreads();

    const int rr  = tid >> 3;
    const int colg = (tid & 7) * 16;
#pragma unroll 1
    for (int pass = 0; pass < 8; pass++) {
        int r = pass * 32 + rr;
        const float* src = &sf[r * 132 + colg];
        if (MODE == 0) {
            float4* dst = (float4*)&Cout[(size_t)(m0 + r) * ND + n0 + colg];
#pragma unroll
            for (int j = 0; j < 4; j++) dst[j] = ((const float4*)src)[j];
        } else {
            int col0 = n0 + colg;
            int part = col0 >> 10;
            int rem  = col0 & 1023;
            int h    = rem >> 6;
            int d0   = rem & 63;
            int m = m0 + r;
            int b = m >> 11, s = m & 2047;
            size_t base = (((size_t)(b * NH + h)) * NS + s) * NDK + d0;
            uint32_t hp[8], lp[8];
#pragma unroll
            for (int j = 0; j < 8; j++) {
                float v0 = src[2*j], v1 = src[2*j+1];
                float h0 = __half2float(__float2half_rn(v0));
                float h1 = __half2float(__float2half_rn(v1));
                hp[j] = packh(v0, v1);
                lp[j] = packh(v0 - h0, v1 - h1);
            }
            if (part == 0) {            // Q: hi + lo (A-operand of QK)
                ((uint4*)&g_Qhi[base])[0] = make_uint4(hp[0], hp[1], hp[2], hp[3]);
                ((uint4*)&g_Qhi[base])[1] = make_uint4(hp[4], hp[5], hp[6], hp[7]);
                ((uint4*)&g_Qlo[base])[0] = make_uint4(lp[0], lp[1], lp[2], lp[3]);
                ((uint4*)&g_Qlo[base])[1] = make_uint4(lp[4], lp[5], lp[6], lp[7]);
            } else if (part == 1) {     // K: hi only (B-operand)
                ((uint4*)&g_Khi[base])[0] = make_uint4(hp[0], hp[1], hp[2], hp[3]);
                ((uint4*)&g_Khi[base])[1] = make_uint4(hp[4], hp[5], hp[6], hp[7]);
            } else {                    // V: hi only (B-operand)
                ((uint4*)&g_Vhi[base])[0] = make_uint4(hp[0], hp[1], hp[2], hp[3]);
                ((uint4*)&g_Vhi[base])[1] = make_uint4(hp[4], hp[5], hp[6], hp[7]);
            }
        }
    }
}

// ---------------------------------------------------------------------------
// Stage 2: causal flash attention, fp16 2-pass mma.sync.
// Q (hi+lo) in registers; K hi-only, V hi-only double-buffered via cp.async.
// QK = (Qh+Ql).Kh  (2 passes);  PV = (Ph+Pl).Vh  (2 passes).
// BQ=128 (8 warps x 16 rows), BK=64; grid = (16 qtiles [reversed], 32 bh)
// ---------------------------------------------------------------------------
#define BQ 128
#define ATTN_STAGE 16384                // K hi 8KB + V hi 8KB
#define ATTN_SMEM_B (32768 + 2*ATTN_STAGE)   // Q hi/lo 32KB + 2 stages = 64KB

__global__ void __launch_bounds__(256, 1)
attn_mma_kernel()
{
    const uint32_t smb = smem_u32(dynsm);
    const int tid = threadIdx.x;
    const int wid = tid >> 5, lane = tid & 31;
    const int qb = 15 - (int)blockIdx.x;      // biggest q-tiles first
    const int bh = blockIdx.y;
    const int q0 = qb * BQ;
    const int nkt = 2*qb + 2;

    const size_t bho = (size_t)bh * NS * NDK;
    const __half* Qhg = g_Qhi + bho;
    const __half* Qlg = g_Qlo + bho;
    const __half* Khg = g_Khi + bho;
    const __half* Vhg = g_Vhi + bho;

    // prologue: Q tile (128 x 64 hi/lo) -> smem [row][d] swizzled
#pragma unroll
    for (int c = 0; c < 4; c++) {
        int linear = c*256 + tid;
        int row = linear >> 3, cb = linear & 7;
        uint32_t sa = smb + row*128 + ((cb ^ (row & 7)) << 4);
        cp16(sa,         Qhg + (size_t)(q0 + row)*NDK + cb*8);
        cp16(sa + 16384, Qlg + (size_t)(q0 + row)*NDK + cb*8);
    }
    auto load_stage = [&](int stage, int k0){
        uint32_t sb = smb + 32768 + stage*ATTN_STAGE;
#pragma unroll
        for (int c = 0; c < 2; c++) {
            int linear = c*256 + tid;
            int row = linear >> 3, cb = linear & 7;
            uint32_t off = row*128 + ((cb ^ (row & 7)) << 4);
            cp16(sb + off,        Khg + (size_t)(k0 + row)*NDK + cb*8);
            cp16(sb + 8192 + off, Vhg + (size_t)(k0 + row)*NDK + cb*8);
        }
        cp_commit();
    };
    load_stage(0, 0);
    asm volatile("cp.async.wait_group 0;" ::: "memory");
    __syncthreads();

    uint32_t qh[4][4], ql[4][4];
    {
        int r = wid*16 + (lane & 15);
#pragma unroll
        for (int ks = 0; ks < 4; ks++) {
            int cb = ks*2 + (lane >> 4);
            uint32_t off = r*128 + (((uint32_t)(cb ^ (r & 7))) << 4);
            ldsm_x4(qh[ks], smb + off);
            ldsm_x4(ql[ks], smb + 16384 + off);
        }
    }

    float o[8][4];
#pragma unroll
    for (int nt = 0; nt < 8; nt++)
#pragma unroll
        for (int f = 0; f < 4; f++) o[nt][f] = 0.f;
    float mrow[2] = {-INFINITY, -INFINITY};
    float lrow[2] = {0.f, 0.f};

#pragma unroll 1
    for (int kt = 0; kt < nkt; kt++) {
        if (kt + 1 < nkt) {
            load_stage((kt + 1) & 1, (kt + 1) * 64);
            asm volatile("cp.async.wait_group 1;" ::: "memory");
        } else {
            asm volatile("cp.async.wait_group 0;" ::: "memory");
        }
        __syncthreads();
        uint32_t sb = smb + 32768 + (kt & 1)*ATTN_STAGE;

        // ---- S = (Qh+Ql).Kh, 16x64 per warp ----
        float s[8][4];
#pragma unroll
        for (int nt = 0; nt < 8; nt++)
#pragma unroll
            for (int f = 0; f < 4; f++) s[nt][f] = 0.f;

#pragma unroll
        for (int ks = 0; ks < 4; ks++) {
#pragma unroll
            for (int half = 0; half < 2; half++) {
                uint32_t kh4[4][2];
                int g = lane >> 3, trow = lane & 7;
#pragma unroll
                for (int p = 0; p < 2; p++) {
                    int nrow = half*32 + (p*2 + (g >> 1))*8 + trow;
                    int kb = ks*2 + (g & 1);
                    uint32_t off = nrow*128 + (((uint32_t)(kb ^ (nrow & 7))) << 4);
                    uint32_t r4[4];
                    ldsm_x4(r4, sb + off);
                    kh4[p*2][0] = r4[0]; kh4[p*2][1] = r4[1];
                    kh4[p*2+1][0] = r4[2]; kh4[p*2+1][1] = r4[3];
                }
#pragma unroll
                for (int nt = 0; nt < 4; nt++)
                    mma_f16(s[half*4 + nt], qh[ks], kh4[nt][0], kh4[nt][1]);
#pragma unroll
                for (int nt = 0; nt < 4; nt++)
                    mma_f16(s[half*4 + nt], ql[ks], kh4[nt][0], kh4[nt][1]);
            }
        }

        // ---- scale + causal mask ----
#pragma unroll
        for (int nt = 0; nt < 8; nt++)
#pragma unroll
            for (int f = 0; f < 4; f++) s[nt][f] *= 0.125f;
        if (kt >= nkt - 2) {
            int lim0 = q0 + wid*16 + (lane >> 2) - kt*64;
#pragma unroll
            for (int nt = 0; nt < 8; nt++) {
                int cb = nt*8 + (lane & 3)*2;
                if (cb     > lim0)     s[nt][0] = -INFINITY;
                if (cb + 1 > lim0)     s[nt][1] = -INFINITY;
                if (cb     > lim0 + 8) s[nt][2] = -INFINITY;
                if (cb + 1 > lim0 + 8) s[nt][3] = -INFINITY;
            }
        }

        // ---- online softmax in fragments; pack P hi/lo (fp16) ----
        uint32_t phi[8][2], plo[8][2];
#pragma unroll
        for (int rh = 0; rh < 2; rh++) {
            float tm = -INFINITY;
#pragma unroll
            for (int nt = 0; nt < 8; nt++)
                tm = fmaxf(tm, fmaxf(s[nt][2*rh], s[nt][2*rh+1]));
            tm = fmaxf(tm, __shfl_xor_sync(0xffffffffu, tm, 1));
            tm = fmaxf(tm, __shfl_xor_sync(0xffffffffu, tm, 2));
            float mn  = fmaxf(mrow[rh], tm);
            float sc  = __expf(mrow[rh] - mn);
            float sum = 0.f;
#pragma unroll
            for (int nt = 0; nt < 8; nt++) {
                float p0 = __expf(s[nt][2*rh]     - mn);
                float p1 = __expf(s[nt][2*rh + 1] - mn);
                sum += p0 + p1;
                float h0 = __half2float(__float2half_rn(p0));
                float h1 = __half2float(__float2half_rn(p1));
                phi[nt][rh] = packh(p0, p1);
                plo[nt][rh] = packh(p0 - h0, p1 - h1);
            }
            sum += __shfl_xor_sync(0xffffffffu, sum, 1);
            sum += __shfl_xor_sync(0xffffffffu, sum, 2);
            lrow[rh] = lrow[rh]*sc + sum;
            mrow[rh] = mn;
#pragma unroll
            for (int nt = 0; nt < 8; nt++) {
                o[nt][2*rh]     *= sc;
                o[nt][2*rh + 1] *= sc;
            }
        }

        // ---- O += (Ph+Pl).Vh, V via ldmatrix.trans on [key][d] ----
#pragma unroll
        for (int ks = 0; ks < 4; ks++) {
            uint32_t aph[4] = {phi[2*ks][0], phi[2*ks][1], phi[2*ks+1][0], phi[2*ks+1][1]};
            uint32_t apl[4] = {plo[2*ks][0], plo[2*ks][1], plo[2*ks+1][0], plo[2*ks+1][1]};
#pragma unroll
            for (int dh = 0; dh < 4; dh++) {
                int r  = 16*ks + (lane & 15);
                int cb = dh*2 + (lane >> 4);
                uint32_t off = r*128 + (((uint32_t)(cb ^ (r & 7))) << 4);
                uint32_t vh[4];
                ldsm_x4_t(vh, sb + 8192 + off);
                mma_f16(o[dh*2],   aph, vh[0], vh[1]);
                mma_f16(o[dh*2+1], aph, vh[2], vh[3]);
                mma_f16(o[dh*2],   apl, vh[0], vh[1]);
                mma_f16(o[dh*2+1], apl, vh[2], vh[3]);
            }
        }
        __syncthreads();
    }

    // ---- epilogue: O / l -> fp16 hi/lo at [b*s][h*dk] ----
    const int b = bh >> 4, h = bh & 15;
#pragma unroll
    for (int rh = 0; rh < 2; rh++) {
        float inv = 1.0f / lrow[rh];
        int qrow = q0 + wid*16 + (lane >> 2) + rh*8;
        size_t rowbase = ((size_t)(b*NS + qrow))*ND + h*NDK;
#pragma unroll
        for (int nt = 0; nt < 8; nt++) {
            float v0 = o[nt][2*rh]     * inv;
            float v1 = o[nt][2*rh + 1] * inv;
            size_t idx = rowbase + nt*8 + (lane & 3)*2;
            float h0 = __half2float(__float2half_rn(v0));
            float h1 = __half2float(__float2half_rn(v1));
            *(uint32_t*)&g_AOhi[idx] = packh(v0, v1);
            *(uint32_t*)&g_AOlo[idx] = packh(v0 - h0, v1 - h1);
        }
    }
}

// ---------------------------------------------------------------------------

extern "C" void kernel_launch(void* const* d_in, const int* in_sizes, int n_in,
                              void* d_out, int out_size)
{
    const float* X    = (const float*)d_in[0];   // [2,2048,1024]
    const float* Wqkv = (const float*)d_in[1];   // [3072,1024]
    const float* Wout = (const float*)d_in[2];   // [1024,1024]
    float* out = (float*)d_out;                  // [2,2048,1024]

    cudaFuncSetAttribute(gemm_split_kernel<1>, cudaFuncAttributeMaxDynamicSharedMemorySize, GEMM_SMEM);
    cudaFuncSetAttribute(gemm_split_kernel<0>, cudaFuncAttributeMaxDynamicSharedMemorySize, GEMM_SMEM);
    cudaFuncSetAttribute(attn_mma_kernel,      cudaFuncAttributeMaxDynamicSharedMemorySize, ATTN_SMEM_B);

    split_convert<<<(MT*ND/4)/256,    256>>>(X,    0, MT*ND/4);
    split_convert<<<(QKV_N*ND/4)/256, 256>>>(Wqkv, 1, QKV_N*ND/4);
    split_convert<<<(ND*ND/4)/256,    256>>>(Wout, 2, ND*ND/4);

    gemm_split_kernel<1><<<dim3(QKV_N/128, MT/256), 256, GEMM_SMEM>>>(nullptr);
    attn_mma_kernel<<<dim3(NS/BQ, NB*NH), 256, ATTN_SMEM_B>>>();
    gemm_split_kernel<0><<<dim3(ND/128, MT/256), 256, GEMM_SMEM>>>(out);
}

// round 16
// speedup vs baseline: 2.0987x; 1.5105x over previous
#include <cuda_runtime.h>
#include <cuda_fp16.h>
#include <math.h>
#include <stdint.h>

#define NS 2048
#define NB 2
#define NH 16
#define NDK 64
#define ND 1024
#define MT (NB*NS)          // 4096 rows total
#define QKV_N (3*ND)        // 3072

// single dynamic-shared symbol for the whole TU (kernels cast as needed)
extern __shared__ char dynsm[];

// Scratch (allocation-free rule: __device__ globals) — all fp16 hi-only
__device__ __half g_Xh[MT*ND];              // X (A of qkv GEMM)
__device__ __half g_Wh[QKV_N*ND];           // Wqkv (B)
__device__ __half g_Oh[ND*ND];              // Wout (B)
__device__ __half g_AOh[MT*ND];             // attn out (A of outproj)
__device__ __half g_Qh[NB*NH*NS*NDK];       // [b][h][s][d]
__device__ __half g_Kh[NB*NH*NS*NDK];
__device__ __half g_Vh[NB*NH*NS*NDK];

// ---------------------------------------------------------------------------
// helpers (portable PTX only: mma.sync / ldmatrix / cp.async — no tcgen05)
// ---------------------------------------------------------------------------
__device__ __forceinline__ uint32_t smem_u32(const void* p){
    uint32_t a;
    asm("{ .reg .u64 t; cvta.to.shared.u64 t, %1; cvt.u32.u64 %0, t; }" : "=r"(a) : "l"(p));
    return a;
}
__device__ __forceinline__ void cp16(uint32_t saddr, const void* g){
    asm volatile("cp.async.cg.shared.global [%0], [%1], 16;" :: "r"(saddr), "l"(g));
}
__device__ __forceinline__ void cp_commit(){
    asm volatile("cp.async.commit_group;" ::: "memory");
}
__device__ __forceinline__ void ldsm_x4(uint32_t r[4], uint32_t addr){
    asm volatile("ldmatrix.sync.aligned.m8n8.x4.shared.b16 {%0,%1,%2,%3}, [%4];"
                 : "=r"(r[0]), "=r"(r[1]), "=r"(r[2]), "=r"(r[3]) : "r"(addr));
}
__device__ __forceinline__ void ldsm_x4_t(uint32_t r[4], uint32_t addr){
    asm volatile("ldmatrix.sync.aligned.m8n8.x4.trans.shared.b16 {%0,%1,%2,%3}, [%4];"
                 : "=r"(r[0]), "=r"(r[1]), "=r"(r[2]), "=r"(r[3]) : "r"(addr));
}
__device__ __forceinline__ void mma_f16(float c[4], const uint32_t a[4],
                                        const uint32_t b0, const uint32_t b1){
    asm volatile(
        "mma.sync.aligned.m16n8k16.row.col.f32.f16.f16.f32 "
        "{%0,%1,%2,%3}, {%4,%5,%6,%7}, {%8,%9}, {%0,%1,%2,%3};"
        : "+f"(c[0]), "+f"(c[1]), "+f"(c[2]), "+f"(c[3])
        : "r"(a[0]), "r"(a[1]), "r"(a[2]), "r"(a[3]), "r"(b0), "r"(b1));
}
__device__ __forceinline__ uint32_t packh(float a, float b){
    __half2 t = __floats2half2_rn(a, b);
    return *(uint32_t*)&t;
}

// ---------------------------------------------------------------------------
// fp32 -> fp16 convert: which 0=X, 1=Wqkv, 2=Wout
// ---------------------------------------------------------------------------
__global__ void __launch_bounds__(256)
split_convert(const float* __restrict__ src, int which, int n4)
{
    int i = blockIdx.x * 256 + threadIdx.x;
    if (i >= n4) return;
    float4 v = ((const float4*)src)[i];
    __half* hi = (which == 0) ? g_Xh : (which == 1) ? g_Wh : g_Oh;
    ((__half2*)hi)[2*i]   = __floats2half2_rn(v.x, v.y);
    ((__half2*)hi)[2*i+1] = __floats2half2_rn(v.z, v.w);
}

// ---------------------------------------------------------------------------
// 1-pass fp16 warp-MMA GEMM: C = A.B^T, K=1024, fp32 accumulate.
// CTA tile 256x128, 8 warps (4m x 2n), warp tile 64x64, 2-stage cp.async.
// MODE 1: A=X, B=Wqkv  -> epilogue packs fp16 Q/K/V at [b][h][s][d].
// MODE 0: A=AO, B=Wout -> Cout fp32.
// ---------------------------------------------------------------------------
#define KC 64
#define A_ARR (256*128)                 // 256 rows x 128B = 32KB
#define B_ARR (128*128)                 // 128 rows x 128B = 16KB
#define STAGE_BYTES (A_ARR + B_ARR)     // 48KB
#define GEMM_SMEM (256*132*4)           // 135168B: epilogue staging (> 2 stages)

template<int MODE>
__global__ void __launch_bounds__(256, 1)
gemm_split_kernel(float* __restrict__ Cout)
{
    char* sm = dynsm;
    const int tid = threadIdx.x;
    const int wid = tid >> 5, lane = tid & 31;
    const int m0 = blockIdx.y * 256;
    const int n0 = blockIdx.x * 128;

    const __half *A, *B;
    if (MODE == 1) { A = g_Xh;  B = g_Wh; }
    else           { A = g_AOh; B = g_Oh; }

    const uint32_t smb = smem_u32(sm);

    const int wm0 = (wid >> 1) * 64;
    const int wn0 = (wid & 1) * 64;

    float acc[4][8][4];
#pragma unroll
    for (int a = 0; a < 4; a++)
#pragma unroll
        for (int b = 0; b < 8; b++)
#pragma unroll
            for (int c = 0; c < 4; c++) acc[a][b][c] = 0.f;

    auto load_stage = [&](int stage, int k0) {
        uint32_t sb = smb + stage * STAGE_BYTES;
#pragma unroll
        for (int c = 0; c < 8; c++) {
            int linear = c * 256 + tid;
            int row = linear >> 3;
            int cb  = linear & 7;
            uint32_t off = row * 128 + ((cb ^ (row & 7)) << 4);
            cp16(sb + off, A + (size_t)(m0 + row) * ND + k0 + cb * 8);
        }
#pragma unroll
        for (int c = 0; c < 4; c++) {
            int linear = c * 256 + tid;
            int row = linear >> 3;
            int cb  = linear & 7;
            uint32_t off = row * 128 + ((cb ^ (row & 7)) << 4);
            cp16(sb + A_ARR + off, B + (size_t)(n0 + row) * ND + k0 + cb * 8);
        }
        cp_commit();
    };

    load_stage(0, 0);

#pragma unroll 1
    for (int i = 0; i < 16; i++) {
        if (i < 15) load_stage((i + 1) & 1, (i + 1) * KC);
        if (i < 15) asm volatile("cp.async.wait_group 1;" ::: "memory");
        else        asm volatile("cp.async.wait_group 0;" ::: "memory");
        __syncthreads();

        uint32_t sb = smb + (i & 1) * STAGE_BYTES;
        uint32_t a_b = sb, b_b = sb + A_ARR;

#pragma unroll
        for (int ks = 0; ks < 4; ks++) {
            uint32_t ah[4][4];
            {
                int row = (lane & 15);
                int kb  = ks * 2 + (lane >> 4);
#pragma unroll
                for (int mt = 0; mt < 4; mt++) {
                    int r = wm0 + mt * 16 + row;
                    uint32_t off = r * 128 + (((uint32_t)(kb ^ (r & 7))) << 4);
                    ldsm_x4(ah[mt], a_b + off);
                }
            }
            int g = lane >> 3, trow = lane & 7;
#pragma unroll
            for (int p = 0; p < 4; p++) {
                int nrow = wn0 + (p * 2 + (g >> 1)) * 8 + trow;
                int kb = ks * 2 + (g & 1);
                uint32_t off = nrow * 128 + (((uint32_t)(kb ^ (nrow & 7))) << 4);
                uint32_t bh[4];
                ldsm_x4(bh, b_b + off);
#pragma unroll
                for (int mt = 0; mt < 4; mt++) {
                    mma_f16(acc[mt][p*2],   ah[mt], bh[0], bh[1]);
                    mma_f16(acc[mt][p*2+1], ah[mt], bh[2], bh[3]);
                }
            }
        }
        __syncthreads();
    }

    // ---- epilogue: acc -> smem (256x132 f32) -> vectorized global ----
    float* sf = (float*)sm;
    const int gq = lane >> 2, tq = lane & 3;
#pragma unroll
    for (int mt = 0; mt < 4; mt++)
#pragma unroll
        for (int nt = 0; nt < 8; nt++) {
            int m = wm0 + mt * 16 + gq;
            int n = wn0 + nt * 8 + 2 * tq;
            sf[m * 132 + n]           = acc[mt][nt][0];
            sf[m * 132 + n + 1]       = acc[mt][nt][1];
            sf[(m + 8) * 132 + n]     = acc[mt][nt][2];
            sf[(m + 8) * 132 + n + 1] = acc[mt][nt][3];
        }
    __syncthreads();

    const int rr  = tid >> 3;
    const int colg = (tid & 7) * 16;
#pragma unroll 1
    for (int pass = 0; pass < 8; pass++) {
        int r = pass * 32 + rr;
        const float* src = &sf[r * 132 + colg];
        if (MODE == 0) {
            float4* dst = (float4*)&Cout[(size_t)(m0 + r) * ND + n0 + colg];
#pragma unroll
            for (int j = 0; j < 4; j++) dst[j] = ((const float4*)src)[j];
        } else {
            int col0 = n0 + colg;
            int part = col0 >> 10;
            int rem  = col0 & 1023;
            int h    = rem >> 6;
            int d0   = rem & 63;
            __half* dst = (part == 0) ? g_Qh : (part == 1) ? g_Kh : g_Vh;
            int m = m0 + r;
            int b = m >> 11, s = m & 2047;
            size_t base = (((size_t)(b * NH + h)) * NS + s) * NDK + d0;
            uint32_t hp[8];
#pragma unroll
            for (int j = 0; j < 8; j++) hp[j] = packh(src[2*j], src[2*j+1]);
            ((uint4*)&dst[base])[0] = make_uint4(hp[0], hp[1], hp[2], hp[3]);
            ((uint4*)&dst[base])[1] = make_uint4(hp[4], hp[5], hp[6], hp[7]);
        }
    }
}

// ---------------------------------------------------------------------------
// Stage 2: causal flash attention, 1-pass fp16 mma.sync, fp32 accumulate.
// Q in registers; K/V double-buffered via cp.async.
// BQ=128 (8 warps x 16 rows), BK=64; grid = (16 qtiles [reversed], 32 bh)
// ---------------------------------------------------------------------------
#define BQ 128
#define ATTN_STAGE 16384                // K 8KB + V 8KB
#define ATTN_SMEM_B (16384 + 2*ATTN_STAGE)   // Q 16KB + 2 stages = 48KB

__global__ void __launch_bounds__(256, 1)
attn_mma_kernel()
{
    const uint32_t smb = smem_u32(dynsm);
    const int tid = threadIdx.x;
    const int wid = tid >> 5, lane = tid & 31;
    const int qb = 15 - (int)blockIdx.x;      // biggest q-tiles first
    const int bh = blockIdx.y;
    const int q0 = qb * BQ;
    const int nkt = 2*qb + 2;

    const size_t bho = (size_t)bh * NS * NDK;
    const __half* Qg = g_Qh + bho;
    const __half* Kg = g_Kh + bho;
    const __half* Vg = g_Vh + bho;

    // prologue: Q tile (128 x 64) -> smem [row][d] swizzled
#pragma unroll
    for (int c = 0; c < 4; c++) {
        int linear = c*256 + tid;
        int row = linear >> 3, cb = linear & 7;
        uint32_t sa = smb + row*128 + ((cb ^ (row & 7)) << 4);
        cp16(sa, Qg + (size_t)(q0 + row)*NDK + cb*8);
    }
    auto load_stage = [&](int stage, int k0){
        uint32_t sb = smb + 16384 + stage*ATTN_STAGE;
#pragma unroll
        for (int c = 0; c < 2; c++) {
            int linear = c*256 + tid;
            int row = linear >> 3, cb = linear & 7;
            uint32_t off = row*128 + ((cb ^ (row & 7)) << 4);
            cp16(sb + off,        Kg + (size_t)(k0 + row)*NDK + cb*8);
            cp16(sb + 8192 + off, Vg + (size_t)(k0 + row)*NDK + cb*8);
        }
        cp_commit();
    };
    load_stage(0, 0);
    asm volatile("cp.async.wait_group 0;" ::: "memory");
    __syncthreads();

    uint32_t qh[4][4];
    {
        int r = wid*16 + (lane & 15);
#pragma unroll
        for (int ks = 0; ks < 4; ks++) {
            int cb = ks*2 + (lane >> 4);
            uint32_t off = r*128 + (((uint32_t)(cb ^ (r & 7))) << 4);
            ldsm_x4(qh[ks], smb + off);
        }
    }

    float o[8][4];
#pragma unroll
    for (int nt = 0; nt < 8; nt++)
#pragma unroll
        for (int f = 0; f < 4; f++) o[nt][f] = 0.f;
    float mrow[2] = {-INFINITY, -INFINITY};
    float lrow[2] = {0.f, 0.f};

#pragma unroll 1
    for (int kt = 0; kt < nkt; kt++) {
        if (kt + 1 < nkt) {
            load_stage((kt + 1) & 1, (kt + 1) * 64);
            asm volatile("cp.async.wait_group 1;" ::: "memory");
        } else {
            asm volatile("cp.async.wait_group 0;" ::: "memory");
        }
        __syncthreads();
        uint32_t sb = smb + 16384 + (kt & 1)*ATTN_STAGE;

        // ---- S = Q.K^T, 16x64 per warp ----
        float s[8][4];
#pragma unroll
        for (int nt = 0; nt < 8; nt++)
#pragma unroll
            for (int f = 0; f < 4; f++) s[nt][f] = 0.f;

#pragma unroll
        for (int ks = 0; ks < 4; ks++) {
#pragma unroll
            for (int half = 0; half < 2; half++) {
                uint32_t kh4[4][2];
                int g = lane >> 3, trow = lane & 7;
#pragma unroll
                for (int p = 0; p < 2; p++) {
                    int nrow = half*32 + (p*2 + (g >> 1))*8 + trow;
                    int kb = ks*2 + (g & 1);
                    uint32_t off = nrow*128 + (((uint32_t)(kb ^ (nrow & 7))) << 4);
                    uint32_t r4[4];
                    ldsm_x4(r4, sb + off);
                    kh4[p*2][0] = r4[0]; kh4[p*2][1] = r4[1];
                    kh4[p*2+1][0] = r4[2]; kh4[p*2+1][1] = r4[3];
                }
#pragma unroll
                for (int nt = 0; nt < 4; nt++)
                    mma_f16(s[half*4 + nt], qh[ks], kh4[nt][0], kh4[nt][1]);
            }
        }

        // ---- scale + causal mask ----
#pragma unroll
        for (int nt = 0; nt < 8; nt++)
#pragma unroll
            for (int f = 0; f < 4; f++) s[nt][f] *= 0.125f;
        if (kt >= nkt - 2) {
            int lim0 = q0 + wid*16 + (lane >> 2) - kt*64;
#pragma unroll
            for (int nt = 0; nt < 8; nt++) {
                int cb = nt*8 + (lane & 3)*2;
                if (cb     > lim0)     s[nt][0] = -INFINITY;
                if (cb + 1 > lim0)     s[nt][1] = -INFINITY;
                if (cb     > lim0 + 8) s[nt][2] = -INFINITY;
                if (cb + 1 > lim0 + 8) s[nt][3] = -INFINITY;
            }
        }

        // ---- online softmax in fragments; pack P (fp16) ----
        uint32_t phi[8][2];
#pragma unroll
        for (int rh = 0; rh < 2; rh++) {
            float tm = -INFINITY;
#pragma unroll
            for (int nt = 0; nt < 8; nt++)
                tm = fmaxf(tm, fmaxf(s[nt][2*rh], s[nt][2*rh+1]));
            tm = fmaxf(tm, __shfl_xor_sync(0xffffffffu, tm, 1));
            tm = fmaxf(tm, __shfl_xor_sync(0xffffffffu, tm, 2));
            float mn  = fmaxf(mrow[rh], tm);
            float sc  = __expf(mrow[rh] - mn);
            float sum = 0.f;
#pragma unroll
            for (int nt = 0; nt < 8; nt++) {
                float p0 = __expf(s[nt][2*rh]     - mn);
                float p1 = __expf(s[nt][2*rh + 1] - mn);
                sum += p0 + p1;
                phi[nt][rh] = packh(p0, p1);
            }
            sum += __shfl_xor_sync(0xffffffffu, sum, 1);
            sum += __shfl_xor_sync(0xffffffffu, sum, 2);
            lrow[rh] = lrow[rh]*sc + sum;
            mrow[rh] = mn;
#pragma unroll
            for (int nt = 0; nt < 8; nt++) {
                o[nt][2*rh]     *= sc;
                o[nt][2*rh + 1] *= sc;
            }
        }

        // ---- O += P.V, V via ldmatrix.trans on [key][d] ----
#pragma unroll
        for (int ks = 0; ks < 4; ks++) {
            uint32_t aph[4] = {phi[2*ks][0], phi[2*ks][1], phi[2*ks+1][0], phi[2*ks+1][1]};
#pragma unroll
            for (int dh = 0; dh < 4; dh++) {
                int r  = 16*ks + (lane & 15);
                int cb = dh*2 + (lane >> 4);
                uint32_t off = r*128 + (((uint32_t)(cb ^ (r & 7))) << 4);
                uint32_t vh[4];
                ldsm_x4_t(vh, sb + 8192 + off);
                mma_f16(o[dh*2],   aph, vh[0], vh[1]);
                mma_f16(o[dh*2+1], aph, vh[2], vh[3]);
            }
        }
        __syncthreads();
    }

    // ---- epilogue: O / l -> fp16 at [b*s][h*dk] ----
    const int b = bh >> 4, h = bh & 15;
#pragma unroll
    for (int rh = 0; rh < 2; rh++) {
        float inv = 1.0f / lrow[rh];
        int qrow = q0 + wid*16 + (lane >> 2) + rh*8;
        size_t rowbase = ((size_t)(b*NS + qrow))*ND + h*NDK;
#pragma unroll
        for (int nt = 0; nt < 8; nt++) {
            float v0 = o[nt][2*rh]     * inv;
            float v1 = o[nt][2*rh + 1] * inv;
            size_t idx = rowbase + nt*8 + (lane & 3)*2;
            *(uint32_t*)&g_AOh[idx] = packh(v0, v1);
        }
    }
}

// ---------------------------------------------------------------------------

extern "C" void kernel_launch(void* const* d_in, const int* in_sizes, int n_in,
                              void* d_out, int out_size)
{
    const float* X    = (const float*)d_in[0];   // [2,2048,1024]
    const float* Wqkv = (const float*)d_in[1];   // [3072,1024]
    const float* Wout = (const float*)d_in[2];   // [1024,1024]
    float* out = (float*)d_out;                  // [2,2048,1024]

    cudaFuncSetAttribute(gemm_split_kernel<1>, cudaFuncAttributeMaxDynamicSharedMemorySize, GEMM_SMEM);
    cudaFuncSetAttribute(gemm_split_kernel<0>, cudaFuncAttributeMaxDynamicSharedMemorySize, GEMM_SMEM);
    cudaFuncSetAttribute(attn_mma_kernel,      cudaFuncAttributeMaxDynamicSharedMemorySize, ATTN_SMEM_B);

    split_convert<<<(MT*ND/4)/256,    256>>>(X,    0, MT*ND/4);
    split_convert<<<(QKV_N*ND/4)/256, 256>>>(Wqkv, 1, QKV_N*ND/4);
    split_convert<<<(ND*ND/4)/256,    256>>>(Wout, 2, ND*ND/4);

    gemm_split_kernel<1><<<dim3(QKV_N/128, MT/256), 256, GEMM_SMEM>>>(nullptr);
    attn_mma_kernel<<<dim3(NS/BQ, NB*NH), 256, ATTN_SMEM_B>>>();
    gemm_split_kernel<0><<<dim3(ND/128, MT/256), 256, GEMM_SMEM>>>(out);
}

// round 17
// speedup vs baseline: 2.1964x; 1.0466x over previous
#include <cuda_runtime.h>
#include <cuda_fp16.h>
#include <math.h>
#include <stdint.h>

#define NS 2048
#define NB 2
#define NH 16
#define NDK 64
#define ND 1024
#define MT (NB*NS)          // 4096 rows total
#define QKV_N (3*ND)        // 3072

// single dynamic-shared symbol for the whole TU (kernels cast as needed)
extern __shared__ char dynsm[];

// Scratch (allocation-free rule: __device__ globals) — all fp16 hi-only
__device__ __half g_Xh[MT*ND];              // X (A of qkv GEMM)
__device__ __half g_Wh[QKV_N*ND];           // Wqkv (B)
__device__ __half g_Oh[ND*ND];              // Wout (B)
__device__ __half g_AOh[MT*ND];             // attn out (A of outproj)
__device__ __half g_Qh[NB*NH*NS*NDK];       // [b][h][s][d]
__device__ __half g_Kh[NB*NH*NS*NDK];
__device__ __half g_Vh[NB*NH*NS*NDK];

// ---------------------------------------------------------------------------
// helpers (portable PTX only: mma.sync / ldmatrix / cp.async — no tcgen05)
// ---------------------------------------------------------------------------
__device__ __forceinline__ uint32_t smem_u32(const void* p){
    uint32_t a;
    asm("{ .reg .u64 t; cvta.to.shared.u64 t, %1; cvt.u32.u64 %0, t; }" : "=r"(a) : "l"(p));
    return a;
}
__device__ __forceinline__ void cp16(uint32_t saddr, const void* g){
    asm volatile("cp.async.cg.shared.global [%0], [%1], 16;" :: "r"(saddr), "l"(g));
}
__device__ __forceinline__ void cp_commit(){
    asm volatile("cp.async.commit_group;" ::: "memory");
}
__device__ __forceinline__ void ldsm_x4(uint32_t r[4], uint32_t addr){
    asm volatile("ldmatrix.sync.aligned.m8n8.x4.shared.b16 {%0,%1,%2,%3}, [%4];"
                 : "=r"(r[0]), "=r"(r[1]), "=r"(r[2]), "=r"(r[3]) : "r"(addr));
}
__device__ __forceinline__ void ldsm_x4_t(uint32_t r[4], uint32_t addr){
    asm volatile("ldmatrix.sync.aligned.m8n8.x4.trans.shared.b16 {%0,%1,%2,%3}, [%4];"
                 : "=r"(r[0]), "=r"(r[1]), "=r"(r[2]), "=r"(r[3]) : "r"(addr));
}
__device__ __forceinline__ void mma_f16(float c[4], const uint32_t a[4],
                                        const uint32_t b0, const uint32_t b1){
    asm volatile(
        "mma.sync.aligned.m16n8k16.row.col.f32.f16.f16.f32 "
        "{%0,%1,%2,%3}, {%4,%5,%6,%7}, {%8,%9}, {%0,%1,%2,%3};"
        : "+f"(c[0]), "+f"(c[1]), "+f"(c[2]), "+f"(c[3])
        : "r"(a[0]), "r"(a[1]), "r"(a[2]), "r"(a[3]), "r"(b0), "r"(b1));
}
__device__ __forceinline__ uint32_t packh(float a, float b){
    __half2 t = __floats2half2_rn(a, b);
    return *(uint32_t*)&t;
}

// ---------------------------------------------------------------------------
// fused fp32 -> fp16 convert of X, Wqkv, Wout (one launch)
// ---------------------------------------------------------------------------
#define N4_X (MT*ND/4)
#define N4_W (QKV_N*ND/4)
#define N4_O (ND*ND/4)

__global__ void __launch_bounds__(256)
convert_all(const float* __restrict__ X, const float* __restrict__ W,
            const float* __restrict__ O)
{
    int i = blockIdx.x * 256 + threadIdx.x;
    const float* src;
    __half* dst;
    int j = i;
    if (i < N4_X)            { src = X; dst = g_Xh; }
    else if (i < N4_X+N4_W)  { src = W; dst = g_Wh; j = i - N4_X; }
    else                     { src = O; dst = g_Oh; j = i - N4_X - N4_W; }
    float4 v = ((const float4*)src)[j];
    ((__half2*)dst)[2*j]   = __floats2half2_rn(v.x, v.y);
    ((__half2*)dst)[2*j+1] = __floats2half2_rn(v.z, v.w);
}

// ---------------------------------------------------------------------------
// 1-pass fp16 warp-MMA GEMM: C = A.B^T, K=1024, fp32 accumulate.
// CTA tile 128x128, 8 warps (2m x 4n), warp tile 64x32, 3-stage cp.async,
// __launch_bounds__(256,2) -> 2 CTAs/SM for cross-CTA latency hiding.
// MODE 1: A=X, B=Wqkv  -> epilogue packs fp16 Q/K/V at [b][h][s][d].
// MODE 0: A=AO, B=Wout -> Cout fp32.
// ---------------------------------------------------------------------------
#define KC 64
#define T_ARR (128*128)                 // 128 rows x 128B = 16KB (A or B)
#define STAGE_BYTES (2*T_ARR)           // 32KB
#define GEMM_SMEM (3*STAGE_BYTES)       // 96KB (epilogue 67.5KB reuses it)

template<int MODE>
__global__ void __launch_bounds__(256, 2)
gemm_split_kernel(float* __restrict__ Cout)
{
    char* sm = dynsm;
    const int tid = threadIdx.x;
    const int wid = tid >> 5, lane = tid & 31;
    const int m0 = blockIdx.y * 128;
    const int n0 = blockIdx.x * 128;

    const __half *A, *B;
    if (MODE == 1) { A = g_Xh;  B = g_Wh; }
    else           { A = g_AOh; B = g_Oh; }

    const uint32_t smb = smem_u32(sm);

    // warp layout: 2 (m) x 4 (n); warp tile 64x32
    const int wm0 = (wid >> 2) * 64;
    const int wn0 = (wid & 3) * 32;

    float acc[4][4][4];
#pragma unroll
    for (int a = 0; a < 4; a++)
#pragma unroll
        for (int b = 0; b < 4; b++)
#pragma unroll
            for (int c = 0; c < 4; c++) acc[a][b][c] = 0.f;

    // ---- loader: 8 x cp16 per thread per stage ----
    auto load_stage = [&](int stage, int k0) {
        uint32_t sb = smb + stage * STAGE_BYTES;
#pragma unroll
        for (int c = 0; c < 4; c++) {
            int linear = c * 256 + tid;      // 0..1023
            int row = linear >> 3;           // 0..127
            int cb  = linear & 7;
            uint32_t off = row * 128 + ((cb ^ (row & 7)) << 4);
            cp16(sb + off,         A + (size_t)(m0 + row) * ND + k0 + cb * 8);
            cp16(sb + T_ARR + off, B + (size_t)(n0 + row) * ND + k0 + cb * 8);
        }
        cp_commit();
    };

    load_stage(0, 0);
    load_stage(1, KC);

#pragma unroll 1
    for (int i = 0; i < 16; i++) {
        if (i < 15) asm volatile("cp.async.wait_group 1;" ::: "memory");
        else        asm volatile("cp.async.wait_group 0;" ::: "memory");
        __syncthreads();
        if (i + 2 < 16) load_stage((i + 2) % 3, (i + 2) * KC);

        uint32_t sb = smb + (i % 3) * STAGE_BYTES;
        uint32_t a_b = sb, b_b = sb + T_ARR;

#pragma unroll
        for (int ks = 0; ks < 4; ks++) {
            uint32_t ah[4][4];
            {
                int row = (lane & 15);
                int kb  = ks * 2 + (lane >> 4);
#pragma unroll
                for (int mt = 0; mt < 4; mt++) {
                    int r = wm0 + mt * 16 + row;
                    uint32_t off = r * 128 + (((uint32_t)(kb ^ (r & 7))) << 4);
                    ldsm_x4(ah[mt], a_b + off);
                }
            }
            int g = lane >> 3, trow = lane & 7;
#pragma unroll
            for (int p = 0; p < 2; p++) {
                int nrow = wn0 + (p * 2 + (g >> 1)) * 8 + trow;
                int kb = ks * 2 + (g & 1);
                uint32_t off = nrow * 128 + (((uint32_t)(kb ^ (nrow & 7))) << 4);
                uint32_t bh[4];
                ldsm_x4(bh, b_b + off);
#pragma unroll
                for (int mt = 0; mt < 4; mt++) {
                    mma_f16(acc[mt][p*2],   ah[mt], bh[0], bh[1]);
                    mma_f16(acc[mt][p*2+1], ah[mt], bh[2], bh[3]);
                }
            }
        }
        __syncthreads();   // stage consumed before its slot is reloaded
    }

    // ---- epilogue: acc -> smem (128x132 f32) -> vectorized global ----
    float* sf = (float*)sm;
    const int gq = lane >> 2, tq = lane & 3;
#pragma unroll
    for (int mt = 0; mt < 4; mt++)
#pragma unroll
        for (int nt = 0; nt < 4; nt++) {
            int m = wm0 + mt * 16 + gq;
            int n = wn0 + nt * 8 + 2 * tq;
            sf[m * 132 + n]           = acc[mt][nt][0];
            sf[m * 132 + n + 1]       = acc[mt][nt][1];
            sf[(m + 8) * 132 + n]     = acc[mt][nt][2];
            sf[(m + 8) * 132 + n + 1] = acc[mt][nt][3];
        }
    __syncthreads();

    const int rr  = tid >> 3;          // 0..31
    const int colg = (tid & 7) * 16;   // 0,16,...,112
#pragma unroll 1
    for (int pass = 0; pass < 4; pass++) {
        int r = pass * 32 + rr;
        const float* src = &sf[r * 132 + colg];
        if (MODE == 0) {
            float4* dst = (float4*)&Cout[(size_t)(m0 + r) * ND + n0 + colg];
#pragma unroll
            for (int j = 0; j < 4; j++) dst[j] = ((const float4*)src)[j];
        } else {
            int col0 = n0 + colg;
            int part = col0 >> 10;
            int rem  = col0 & 1023;
            int h    = rem >> 6;
            int d0   = rem & 63;
            __half* dst = (part == 0) ? g_Qh : (part == 1) ? g_Kh : g_Vh;
            int m = m0 + r;
            int b = m >> 11, s = m & 2047;
            size_t base = (((size_t)(b * NH + h)) * NS + s) * NDK + d0;
            uint32_t hp[8];
#pragma unroll
            for (int j = 0; j < 8; j++) hp[j] = packh(src[2*j], src[2*j+1]);
            ((uint4*)&dst[base])[0] = make_uint4(hp[0], hp[1], hp[2], hp[3]);
            ((uint4*)&dst[base])[1] = make_uint4(hp[4], hp[5], hp[6], hp[7]);
        }
    }
}

// ---------------------------------------------------------------------------
// Stage 2: causal flash attention, 1-pass fp16 mma.sync, fp32 accumulate.
// Q in registers; K/V double-buffered via cp.async; 2 CTAs/SM.
// BQ=128 (8 warps x 16 rows), BK=64; grid = (16 qtiles [reversed], 32 bh)
// ---------------------------------------------------------------------------
#define BQ 128
#define ATTN_STAGE 16384                // K 8KB + V 8KB
#define ATTN_SMEM_B (16384 + 2*ATTN_STAGE)   // Q 16KB + 2 stages = 48KB

__global__ void __launch_bounds__(256, 2)
attn_mma_kernel()
{
    const uint32_t smb = smem_u32(dynsm);
    const int tid = threadIdx.x;
    const int wid = tid >> 5, lane = tid & 31;
    const int qb = 15 - (int)blockIdx.x;      // biggest q-tiles first
    const int bh = blockIdx.y;
    const int q0 = qb * BQ;
    const int nkt = 2*qb + 2;

    const size_t bho = (size_t)bh * NS * NDK;
    const __half* Qg = g_Qh + bho;
    const __half* Kg = g_Kh + bho;
    const __half* Vg = g_Vh + bho;

    // prologue: Q tile (128 x 64) -> smem [row][d] swizzled
#pragma unroll
    for (int c = 0; c < 4; c++) {
        int linear = c*256 + tid;
        int row = linear >> 3, cb = linear & 7;
        uint32_t sa = smb + row*128 + ((cb ^ (row & 7)) << 4);
        cp16(sa, Qg + (size_t)(q0 + row)*NDK + cb*8);
    }
    auto load_stage = [&](int stage, int k0){
        uint32_t sb = smb + 16384 + stage*ATTN_STAGE;
#pragma unroll
        for (int c = 0; c < 2; c++) {
            int linear = c*256 + tid;
            int row = linear >> 3, cb = linear & 7;
            uint32_t off = row*128 + ((cb ^ (row & 7)) << 4);
            cp16(sb + off,        Kg + (size_t)(k0 + row)*NDK + cb*8);
            cp16(sb + 8192 + off, Vg + (size_t)(k0 + row)*NDK + cb*8);
        }
        cp_commit();
    };
    load_stage(0, 0);
    asm volatile("cp.async.wait_group 0;" ::: "memory");
    __syncthreads();

    uint32_t qh[4][4];
    {
        int r = wid*16 + (lane & 15);
#pragma unroll
        for (int ks = 0; ks < 4; ks++) {
            int cb = ks*2 + (lane >> 4);
            uint32_t off = r*128 + (((uint32_t)(cb ^ (r & 7))) << 4);
            ldsm_x4(qh[ks], smb + off);
        }
    }

    float o[8][4];
#pragma unroll
    for (int nt = 0; nt < 8; nt++)
#pragma unroll
        for (int f = 0; f < 4; f++) o[nt][f] = 0.f;
    float mrow[2] = {-INFINITY, -INFINITY};
    float lrow[2] = {0.f, 0.f};

#pragma unroll 1
    for (int kt = 0; kt < nkt; kt++) {
        if (kt + 1 < nkt) {
            load_stage((kt + 1) & 1, (kt + 1) * 64);
            asm volatile("cp.async.wait_group 1;" ::: "memory");
        } else {
            asm volatile("cp.async.wait_group 0;" ::: "memory");
        }
        __syncthreads();
        uint32_t sb = smb + 16384 + (kt & 1)*ATTN_STAGE;

        // ---- S = Q.K^T, 16x64 per warp ----
        float s[8][4];
#pragma unroll
        for (int nt = 0; nt < 8; nt++)
#pragma unroll
            for (int f = 0; f < 4; f++) s[nt][f] = 0.f;

#pragma unroll
        for (int ks = 0; ks < 4; ks++) {
#pragma unroll
            for (int half = 0; half < 2; half++) {
                uint32_t kh4[4][2];
                int g = lane >> 3, trow = lane & 7;
#pragma unroll
                for (int p = 0; p < 2; p++) {
                    int nrow = half*32 + (p*2 + (g >> 1))*8 + trow;
                    int kb = ks*2 + (g & 1);
                    uint32_t off = nrow*128 + (((uint32_t)(kb ^ (nrow & 7))) << 4);
                    uint32_t r4[4];
                    ldsm_x4(r4, sb + off);
                    kh4[p*2][0] = r4[0]; kh4[p*2][1] = r4[1];
                    kh4[p*2+1][0] = r4[2]; kh4[p*2+1][1] = r4[3];
                }
#pragma unroll
                for (int nt = 0; nt < 4; nt++)
                    mma_f16(s[half*4 + nt], qh[ks], kh4[nt][0], kh4[nt][1]);
            }
        }

        // ---- scale + causal mask ----
#pragma unroll
        for (int nt = 0; nt < 8; nt++)
#pragma unroll
            for (int f = 0; f < 4; f++) s[nt][f] *= 0.125f;
        if (kt >= nkt - 2) {
            int lim0 = q0 + wid*16 + (lane >> 2) - kt*64;
#pragma unroll
            for (int nt = 0; nt < 8; nt++) {
                int cb = nt*8 + (lane & 3)*2;
                if (cb     > lim0)     s[nt][0] = -INFINITY;
                if (cb + 1 > lim0)     s[nt][1] = -INFINITY;
                if (cb     > lim0 + 8) s[nt][2] = -INFINITY;
                if (cb + 1 > lim0 + 8) s[nt][3] = -INFINITY;
            }
        }

        // ---- online softmax in fragments; pack P (fp16) ----
        uint32_t phi[8][2];
#pragma unroll
        for (int rh = 0; rh < 2; rh++) {
            float tm = -INFINITY;
#pragma unroll
            for (int nt = 0; nt < 8; nt++)
                tm = fmaxf(tm, fmaxf(s[nt][2*rh], s[nt][2*rh+1]));
            tm = fmaxf(tm, __shfl_xor_sync(0xffffffffu, tm, 1));
            tm = fmaxf(tm, __shfl_xor_sync(0xffffffffu, tm, 2));
            float mn  = fmaxf(mrow[rh], tm);
            float sc  = __expf(mrow[rh] - mn);
            float sum = 0.f;
#pragma unroll
            for (int nt = 0; nt < 8; nt++) {
                float p0 = __expf(s[nt][2*rh]     - mn);
                float p1 = __expf(s[nt][2*rh + 1] - mn);
                sum += p0 + p1;
                phi[nt][rh] = packh(p0, p1);
            }
            sum += __shfl_xor_sync(0xffffffffu, sum, 1);
            sum += __shfl_xor_sync(0xffffffffu, sum, 2);
            lrow[rh] = lrow[rh]*sc + sum;
            mrow[rh] = mn;
#pragma unroll
            for (int nt = 0; nt < 8; nt++) {
                o[nt][2*rh]     *= sc;
                o[nt][2*rh + 1] *= sc;
            }
        }

        // ---- O += P.V, V via ldmatrix.trans on [key][d] ----
#pragma unroll
        for (int ks = 0; ks < 4; ks++) {
            uint32_t aph[4] = {phi[2*ks][0], phi[2*ks][1], phi[2*ks+1][0], phi[2*ks+1][1]};
#pragma unroll
            for (int dh = 0; dh < 4; dh++) {
                int r  = 16*ks + (lane & 15);
                int cb = dh*2 + (lane >> 4);
                uint32_t off = r*128 + (((uint32_t)(cb ^ (r & 7))) << 4);
                uint32_t vh[4];
                ldsm_x4_t(vh, sb + 8192 + off);
                mma_f16(o[dh*2],   aph, vh[0], vh[1]);
                mma_f16(o[dh*2+1], aph, vh[2], vh[3]);
            }
        }
        __syncthreads();
    }

    // ---- epilogue: O / l -> fp16 at [b*s][h*dk] ----
    const int b = bh >> 4, h = bh & 15;
#pragma unroll
    for (int rh = 0; rh < 2; rh++) {
        float inv = 1.0f / lrow[rh];
        int qrow = q0 + wid*16 + (lane >> 2) + rh*8;
        size_t rowbase = ((size_t)(b*NS + qrow))*ND + h*NDK;
#pragma unroll
        for (int nt = 0; nt < 8; nt++) {
            float v0 = o[nt][2*rh]     * inv;
            float v1 = o[nt][2*rh + 1] * inv;
            size_t idx = rowbase + nt*8 + (lane & 3)*2;
            *(uint32_t*)&g_AOh[idx] = packh(v0, v1);
        }
    }
}

// ---------------------------------------------------------------------------

extern "C" void kernel_launch(void* const* d_in, const int* in_sizes, int n_in,
                              void* d_out, int out_size)
{
    const float* X    = (const float*)d_in[0];   // [2,2048,1024]
    const float* Wqkv = (const float*)d_in[1];   // [3072,1024]
    const float* Wout = (const float*)d_in[2];   // [1024,1024]
    float* out = (float*)d_out;                  // [2,2048,1024]

    cudaFuncSetAttribute(gemm_split_kernel<1>, cudaFuncAttributeMaxDynamicSharedMemorySize, GEMM_SMEM);
    cudaFuncSetAttribute(gemm_split_kernel<0>, cudaFuncAttributeMaxDynamicSharedMemorySize, GEMM_SMEM);
    cudaFuncSetAttribute(attn_mma_kernel,      cudaFuncAttributeMaxDynamicSharedMemorySize, ATTN_SMEM_B);

    convert_all<<<(N4_X + N4_W + N4_O) / 256, 256>>>(X, Wqkv, Wout);

    gemm_split_kernel<1><<<dim3(QKV_N/128, MT/128), 256, GEMM_SMEM>>>(nullptr);
    attn_mma_kernel<<<dim3(NS/BQ, NB*NH), 256, ATTN_SMEM_B>>>();
    gemm_split_kernel<0><<<dim3(ND/128, MT/128), 256, GEMM_SMEM>>>(out);
}